// round 13
// baseline (speedup 1.0000x reference)
#include <cuda_runtime.h>
#include <math.h>

#define MM 4096
#define WORDD 4096
#define NWH 2
#define RH 4
#define EPSV 0.001f
#define LCHUNK 64
#define LNCH 64   // 4096 / LCHUNK

// ---------------- scratch (device globals; allocation-free) ----------------
__device__ __align__(16) float g_wv[NWH*WORDD];
__device__ __align__(16) float g_ev[NWH*WORDD];
__device__ __align__(16) float g_wk[NWH*WORDD];
__device__ __align__(16) float g_rk[RH*WORDD];
__device__ __align__(16) float g_small[64]; // fg[0..3] ag[4..5] wg[6..7] rm[8..27] ws[28..29] rs[30..33]
__device__ __align__(16) float g_dot[NWH*MM];
__device__ __align__(16) float g_memnorm[MM];
__device__ __align__(16) float g_cw[NWH*MM];
__device__ __align__(16) float g_alloc[NWH*MM];
__device__ __align__(16) float g_ww[NWH*MM];
__device__ __align__(16) float g_usageA[MM];
__device__ __align__(16) float g_usageB[MM];
__device__ __align__(16) float g_sortedu[MM];
__device__ __align__(16) int   g_rankidx[MM];
__device__ __align__(16) float g_rdot[RH*MM];
__device__ __align__(16) float g_newnorm[MM];
__device__ __align__(16) float g_fwd[RH*NWH*MM];
__device__ __align__(16) float g_bwd[RH*NWH*MM];
__device__ __align__(16) float g_rw[RH*MM];
__device__ __align__(16) float g_part_bwd[NWH*LNCH*RH*MM];  // 8 MB fixed-order partials
__device__ __align__(16) float g_part_rw[16*RH*WORDD];      // 1 MB

__device__ __forceinline__ float wred(float v){
    #pragma unroll
    for (int o=16;o;o>>=1) v += __shfl_xor_sync(0xFFFFFFFFu,v,o);
    return v;
}
__device__ __forceinline__ float gred4(float a, float b, float c, float d, int lane){
    float x1 = (lane&16)? a : c;
    float x2 = (lane&16)? b : d;
    float r1 = __shfl_xor_sync(0xFFFFFFFFu, x1, 16);
    float r2 = __shfl_xor_sync(0xFFFFFFFFu, x2, 16);
    float va = ((lane&16)? c : a) + r1;
    float vb = ((lane&16)? d : b) + r2;
    float y = (lane&8)? va : vb;
    float r = __shfl_xor_sync(0xFFFFFFFFu, y, 8);
    float v = ((lane&8)? vb : va) + r;
    #pragma unroll
    for (int o=4;o;o>>=1) v += __shfl_xor_sync(0xFFFFFFFFu, v, o);
    return v;
}
__device__ __forceinline__ float gred2(float a, float b, int lane){
    float x = (lane&16)? a : b;
    float r = __shfl_xor_sync(0xFFFFFFFFu, x, 16);
    float v = ((lane&16)? b : a) + r;
    #pragma unroll
    for (int o=8;o;o>>=1) v += __shfl_xor_sync(0xFFFFFFFFu, v, o);
    return v;
}

// ---------------- kernel 1: all linear layers (warp-per-row matvec) --------
__global__ void k_matvec(const float* __restrict__ x,
    const float* __restrict__ Wwv, const float* __restrict__ bwv,
    const float* __restrict__ Wev, const float* __restrict__ bev,
    const float* __restrict__ Wfg, const float* __restrict__ bfg,
    const float* __restrict__ Wag, const float* __restrict__ bag,
    const float* __restrict__ Wwg, const float* __restrict__ bwg,
    const float* __restrict__ Wrm, const float* __restrict__ brm,
    const float* __restrict__ Wwk, const float* __restrict__ bwk,
    const float* __restrict__ Wws, const float* __restrict__ bws,
    const float* __restrict__ Wrk, const float* __restrict__ brk,
    const float* __restrict__ Wrs, const float* __restrict__ brs)
{
    int warp = (blockIdx.x*blockDim.x + threadIdx.x) >> 5;
    int lane = threadIdx.x & 31;
    if (warp >= 40994) return;
    const float* W; const float* b; float* out; int row; int act;
    if (warp < 8192)       { W=Wwv; b=bwv; out=g_wv; row=warp;       act=0; }
    else if (warp < 16384) { W=Wev; b=bev; out=g_ev; row=warp-8192;  act=1; }
    else if (warp < 24576) { W=Wwk; b=bwk; out=g_wk; row=warp-16384; act=1; }
    else if (warp < 40960) { W=Wrk; b=brk; out=g_rk; row=warp-24576; act=0; }
    else {
        int r = warp - 40960;
        if (r < 4)       { W=Wfg; b=bfg; out=g_small+0;  row=r;    act=1; }
        else if (r < 6)  { W=Wag; b=bag; out=g_small+4;  row=r-4;  act=1; }
        else if (r < 8)  { W=Wwg; b=bwg; out=g_small+6;  row=r-6;  act=1; }
        else if (r < 28) { W=Wrm; b=brm; out=g_small+8;  row=r-8;  act=1; }
        else if (r < 30) { W=Wws; b=bws; out=g_small+28; row=r-28; act=0; }
        else             { W=Wrs; b=brs; out=g_small+30; row=r-30; act=0; }
    }
    const float4* Wr = (const float4*)(W + (size_t)row*1024);
    const float4* x4 = (const float4*)x;
    float s = 0.f;
    #pragma unroll 8
    for (int i = lane; i < 256; i += 32) {
        float4 w4 = Wr[i], xx = x4[i];
        s += w4.x*xx.x + w4.y*xx.y + w4.z*xx.z + w4.w*xx.w;
    }
    s = wred(s);
    if (lane==0) {
        s += b[row];
        if (act) s = 1.f/(1.f+expf(-s));
        out[row] = s;
    }
}

// ------------- kernel 2: dot(write_keys, memory) + memory row norms --------
__global__ void __launch_bounds__(1024) k_memdot(const float* __restrict__ memory) {
    __shared__ float s_part[32][3*32];
    int tid = threadIdx.x, lane = tid&31, wid = tid>>5;
    const float4* wk4 = (const float4*)g_wk;
    float4 k0 = __ldg(&wk4[tid]);
    float4 k1 = __ldg(&wk4[1024+tid]);
    int base = blockIdx.x*32;
    float4 vA_n = __ldg((const float4*)(memory + (size_t)base*WORDD) + tid);
    float4 vB_n = __ldg((const float4*)(memory + (size_t)(base+1)*WORDD) + tid);
    #pragma unroll 1
    for (int ii = 0; ii < 32; ii += 2) {
        float4 vA = vA_n, vB = vB_n;
        if (ii < 30) {
            vA_n = __ldg((const float4*)(memory + (size_t)(base+ii+2)*WORDD) + tid);
            vB_n = __ldg((const float4*)(memory + (size_t)(base+ii+3)*WORDD) + tid);
        }
        float dA0 = vA.x*k0.x+vA.y*k0.y+vA.z*k0.z+vA.w*k0.w;
        float dA1 = vA.x*k1.x+vA.y*k1.y+vA.z*k1.z+vA.w*k1.w;
        float nnA = vA.x*vA.x+vA.y*vA.y+vA.z*vA.z+vA.w*vA.w;
        float dB0 = vB.x*k0.x+vB.y*k0.y+vB.z*k0.z+vB.w*k0.w;
        float dB1 = vB.x*k1.x+vB.y*k1.y+vB.z*k1.z+vB.w*k1.w;
        float nnB = vB.x*vB.x+vB.y*vB.y+vB.z*vB.z+vB.w*vB.w;
        float dv = gred4(dA0,dA1,dB0,dB1,lane);
        float nv = gred2(nnA,nnB,lane);
        if (lane==0)  s_part[ii][wid]      = dv;
        if (lane==8)  s_part[ii][32+wid]   = dv;
        if (lane==16) s_part[ii+1][wid]    = dv;
        if (lane==24) s_part[ii+1][32+wid] = dv;
        if (lane==0)  s_part[ii][64+wid]   = nv;
        if (lane==16) s_part[ii+1][64+wid] = nv;
    }
    __syncthreads();
    if (tid < 96) {
        int row = tid/3, q = tid - row*3;
        float s = 0.f;
        #pragma unroll
        for (int k=0;k<32;k++) s += s_part[row][q*32+k];
        int m = base + row;
        if (q==0) g_dot[m]=s; else if (q==1) g_dot[MM+m]=s; else g_memnorm[m]=sqrtf(s);
    }
}

// ------------- kernel 3a: content weights (per write head, parallel) -------
__global__ void k_cw(){
    __shared__ float red[32];
    __shared__ float s_bc;
    const int T = 1024;
    int tid=threadIdx.x, lane=tid&31, wid=tid>>5;
    int head = blockIdx.x;
    float kn=0.f;
    for (int d=tid; d<WORDD; d+=T){ float k = g_wk[head*WORDD+d]; kn += k*k; }
    kn = wred(kn);
    if (lane==0) red[wid]=kn;
    __syncthreads();
    if (tid==0){ float s=0; for(int k=0;k<32;k++) s+=red[k]; s_bc = sqrtf(s);}
    __syncthreads();
    kn = s_bc;
    float ws = g_small[28+head];
    float beta = 1.f + log1pf(expf(ws));
    float mx = -3.4e38f;
    for (int m=tid;m<MM;m+=T){
        float l = g_dot[head*MM+m]/(kn*g_memnorm[m]+EPSV)*beta;
        mx = fmaxf(mx,l);
    }
    #pragma unroll
    for (int o=16;o;o>>=1) mx = fmaxf(mx,__shfl_xor_sync(0xFFFFFFFFu,mx,o));
    if (lane==0) red[wid]=mx;
    __syncthreads();
    if (tid==0){ float s=-3.4e38f; for(int k=0;k<32;k++) s=fmaxf(s,red[k]); s_bc=s;}
    __syncthreads();
    mx = s_bc;
    float sume=0.f;
    for (int m=tid;m<MM;m+=T){
        float l = g_dot[head*MM+m]/(kn*g_memnorm[m]+EPSV)*beta;
        float e = expf(l-mx);
        g_cw[head*MM+m]=e; sume+=e;
    }
    sume = wred(sume);
    if (lane==0) red[wid]=sume;
    __syncthreads();
    if (tid==0){ float s=0; for(int k=0;k<32;k++) s+=red[k]; s_bc=s;}
    __syncthreads();
    float inv = 1.f/s_bc;
    for (int m=tid;m<MM;m+=T) g_cw[head*MM+m] *= inv;
}

// ------------- kernel 3b: initial usage ------------------------------------
__global__ void k_usage(const float* __restrict__ prev_rw,
                        const float* __restrict__ prev_ww,
                        const float* __restrict__ prev_usage){
    int m = blockIdx.x*1024 + threadIdx.x;
    float fg0=g_small[0],fg1=g_small[1],fg2=g_small[2],fg3=g_small[3];
    float u = prev_usage[m];
    u = u + (1.f-u)*(1.f - prev_ww[m]*prev_ww[MM+m]);
    float p = (fg0*prev_rw[m])*(fg1*prev_rw[MM+m])*(fg2*prev_rw[2*MM+m])*(fg3*prev_rw[3*MM+m]);
    g_usageA[m] = u*(1.f - p);
}

// ------------- kernel 3c: all-pairs rank (replaces bitonic sort) -----------
// which: 0 -> read g_usageA, 1 -> read g_usageB. Device-side symbol selection
// (host-passed __device__ symbols resolve to host shadow under ATS!).
__global__ void __launch_bounds__(1024) k_rank(int which){
    __shared__ float s_u[MM];
    const float* usage_in = which ? g_usageB : g_usageA;
    int tid = threadIdx.x;
    for (int m=tid;m<MM;m+=1024) s_u[m] = EPSV + (1.f-EPSV)*usage_in[m];
    __syncthreads();
    int m = blockIdx.x*1024 + tid;
    float um = s_u[m];
    int cnt = 0;
    const float4* su4 = (const float4*)s_u;
    #pragma unroll 4
    for (int j4=0;j4<1024;j4++){
        float4 v = su4[j4];
        int j = j4<<2;
        cnt += (v.x<um) || (v.x==um && (j+0)<m);
        cnt += (v.y<um) || (v.y==um && (j+1)<m);
        cnt += (v.z<um) || (v.z==um && (j+2)<m);
        cnt += (v.w<um) || (v.w==um && (j+3)<m);
    }
    g_sortedu[cnt] = um;
    g_rankidx[m] = cnt;
}

// ------------- kernel 3d: cumprod scan over sorted u + alloc + usage upd ---
__global__ void __launch_bounds__(1024) k_scan(int head,
                                               float* __restrict__ out_usage_final){
    __shared__ float s_alloc[MM];
    __shared__ float s_wsum2[32];
    __shared__ float s_wpre[32];
    const float* usage_in = head ? g_usageB : g_usageA;
    int tid=threadIdx.x, lane=tid&31, wid=tid>>5;
    int base = tid*4;
    float4 xv = *(const float4*)(g_sortedu + base);
    float x0=xv.x, x1=xv.y, x2=xv.z, x3=xv.w;
    float c0=x0, c1=c0*x1, c2=c1*x2, c3=c2*x3;
    float t3=c3;
    #pragma unroll
    for (int o=1;o<32;o<<=1){ float n=__shfl_up_sync(0xFFFFFFFFu,t3,o); if (lane>=o) t3*=n; }
    float warpExcl = __shfl_up_sync(0xFFFFFFFFu,t3,1); if (lane==0) warpExcl=1.f;
    if (lane==31) s_wsum2[wid]=t3;
    __syncthreads();
    if (tid<32){
        float w = s_wsum2[tid];
        float tw=w;
        #pragma unroll
        for (int o=1;o<32;o<<=1){ float n=__shfl_up_sync(0xFFFFFFFFu,tw,o); if (tid>=o) tw*=n; }
        float excl = __shfl_up_sync(0xFFFFFFFFu,tw,1); if (tid==0) excl=1.f;
        s_wpre[tid]=excl;
    }
    __syncthreads();
    float pre = s_wpre[wid]*warpExcl;
    s_alloc[base+0]=(1.f-x0)*pre;
    s_alloc[base+1]=(1.f-x1)*pre*c0;
    s_alloc[base+2]=(1.f-x2)*pre*c1;
    s_alloc[base+3]=(1.f-x3)*pre*c2;
    __syncthreads();
    float ag=g_small[4+head], wg=g_small[6+head];
    float agwg = ag*wg;
    for (int m=tid;m<MM;m+=1024){
        float a = s_alloc[g_rankidx[m]];
        g_alloc[head*MM+m] = a;
        float u = usage_in[m];
        float nu = u + (1.f - u)*agwg*a;
        if (head==0) g_usageB[m] = nu; else out_usage_final[m] = nu;
    }
}

// ------------- kernel 3e: write weights + precedence (per head) ------------
__global__ void k_wwprec(const float* __restrict__ prev_prec,
                         float* __restrict__ out_ww,
                         float* __restrict__ out_prec)
{
    __shared__ float red[32];
    __shared__ float s_bc;
    const int T = 1024;
    int tid=threadIdx.x, lane=tid&31, wid=tid>>5;
    int head = blockIdx.x;
    float ag = g_small[4+head], wg = g_small[6+head];
    float wsum = 0.f;
    for (int m=tid;m<MM;m+=T){
        float a = g_alloc[head*MM+m];
        float cw = g_cw[head*MM+m];
        float w = wg*(ag*a + (1.f-ag)*cw);
        g_ww[head*MM+m] = w;
        out_ww[head*MM+m] = w;
        wsum += w;
    }
    wsum = wred(wsum);
    if (lane==0) red[wid]=wsum;
    __syncthreads();
    if (tid==0){ float s=0; for(int k=0;k<32;k++) s+=red[k]; s_bc=s;}
    __syncthreads();
    float oms = 1.f - s_bc;
    for (int m=tid;m<MM;m+=T)
        out_prec[head*MM+m] = oms*prev_prec[head*MM+m] + g_ww[head*MM+m];
}

// ------------- kernel 4: new_memory + fused rdot + new norms ---------------
__global__ void __launch_bounds__(1024) k_newmem(const float* __restrict__ memory,
                                                 float* __restrict__ out_nm){
    __shared__ float s_part[32][5*32];
    int tid=threadIdx.x, lane=tid&31, wid=tid>>5;
    const float4* ev4=(const float4*)g_ev;
    const float4* wv4=(const float4*)g_wv;
    const float4* rk4=(const float4*)g_rk;
    float4 e0=__ldg(&ev4[tid]),      e1=__ldg(&ev4[1024+tid]);
    float4 a0=__ldg(&wv4[tid]),      a1=__ldg(&wv4[1024+tid]);
    float4 k0=__ldg(&rk4[tid]),      k1=__ldg(&rk4[1024+tid]);
    float4 k2=__ldg(&rk4[2048+tid]), k3=__ldg(&rk4[3072+tid]);
    int base = blockIdx.x*32;
    float4 v_next = __ldg((const float4*)(memory+(size_t)base*WORDD) + tid);
    #pragma unroll 1
    for (int ii=0; ii<32; ii++){
        int m = base+ii;
        float4 v = v_next;
        if (ii<31) v_next = __ldg((const float4*)(memory+(size_t)(m+1)*WORDD) + tid);
        float w0=__ldg(&g_ww[m]), w1=__ldg(&g_ww[MM+m]);
        float4 o;
        o.x = v.x*((1.f-w0*e0.x)*(1.f-w1*e1.x)) + w0*a0.x + w1*a1.x;
        o.y = v.y*((1.f-w0*e0.y)*(1.f-w1*e1.y)) + w0*a0.y + w1*a1.y;
        o.z = v.z*((1.f-w0*e0.z)*(1.f-w1*e1.z)) + w0*a0.z + w1*a1.z;
        o.w = v.w*((1.f-w0*e0.w)*(1.f-w1*e1.w)) + w0*a0.w + w1*a1.w;
        ((float4*)(out_nm+(size_t)m*WORDD))[tid]=o;
        float r0 = o.x*k0.x+o.y*k0.y+o.z*k0.z+o.w*k0.w;
        float r1 = o.x*k1.x+o.y*k1.y+o.z*k1.z+o.w*k1.w;
        float r2 = o.x*k2.x+o.y*k2.y+o.z*k2.z+o.w*k2.w;
        float r3 = o.x*k3.x+o.y*k3.y+o.z*k3.z+o.w*k3.w;
        float nn = o.x*o.x+o.y*o.y+o.z*o.z+o.w*o.w;
        float rv = gred4(r0,r1,r2,r3,lane);
        float nv = wred(nn);
        if ((lane&7)==0) s_part[ii][(lane>>3)*32+wid] = rv;
        if (lane==0)     s_part[ii][128+wid] = nv;
    }
    __syncthreads();
    if (tid < 160){
        int row=tid/5, q=tid-row*5;
        float s=0.f;
        #pragma unroll
        for (int k=0;k<32;k++) s += s_part[row][q*32+k];
        int m = base + row;
        if (q<4) g_rdot[q*MM+m]=s; else g_newnorm[m]=sqrtf(s);
    }
}

// ------------- kernel 5: link update + fused fwd_w/bwd_w -------------------
__global__ void __launch_bounds__(512) k_link(const float* __restrict__ prev_link,
                       const float* __restrict__ prev_prec,
                       const float* __restrict__ prev_rw,
                       float* __restrict__ out_link){
    __shared__ float s_fred[LCHUNK][4][16];
    int w = blockIdx.y;
    int chunk = blockIdx.x;
    int i0 = chunk*LCHUNK;
    int tid=threadIdx.x, lane=tid&31, wid=tid>>5;
    const float4* ww4 = (const float4*)(g_ww + w*MM);
    const float4* pp4 = (const float4*)(prev_prec + w*MM);
    const float4* pr4 = (const float4*)prev_rw;
    float4 wwa=__ldg(&ww4[tid]),       wwb=__ldg(&ww4[512+tid]);
    float4 ppa=__ldg(&pp4[tid]),       ppb=__ldg(&pp4[512+tid]);
    float4 pa0=__ldg(&pr4[tid]),       pb0=__ldg(&pr4[512+tid]);
    float4 pa1=__ldg(&pr4[1024+tid]),  pb1=__ldg(&pr4[1536+tid]);
    float4 pa2=__ldg(&pr4[2048+tid]),  pb2=__ldg(&pr4[2560+tid]);
    float4 pa3=__ldg(&pr4[3072+tid]),  pb3=__ldg(&pr4[3584+tid]);
    float bw0[8],bw1[8],bw2[8],bw3[8];
    #pragma unroll
    for (int c=0;c<8;c++){ bw0[c]=0.f;bw1[c]=0.f;bw2[c]=0.f;bw3[c]=0.f; }
    int ja = tid*4, jb = (512+tid)*4;
    const float4* plbase = (const float4*)(prev_link + (size_t)w*MM*MM);
    float4 pA_n = __ldcs(plbase + (size_t)i0*1024 + tid);
    float4 pB_n = __ldcs(plbase + (size_t)i0*1024 + 512 + tid);
    #pragma unroll 1
    for (int ii=0; ii<LCHUNK; ii++){
        int i = i0+ii;
        float4 pA = pA_n, pB = pB_n;
        if (ii<LCHUNK-1){
            pA_n = __ldcs(plbase + (size_t)(i+1)*1024 + tid);
            pB_n = __ldcs(plbase + (size_t)(i+1)*1024 + 512 + tid);
        }
        float wwi = __ldg(&g_ww[w*MM+i]);
        float pri0=__ldg(&prev_rw[i]),      pri1=__ldg(&prev_rw[MM+i]);
        float pri2=__ldg(&prev_rw[2*MM+i]), pri3=__ldg(&prev_rw[3*MM+i]);
        float f0=0.f,f1=0.f,f2=0.f,f3=0.f;
        float4 oA, oB;
        {
            float l = (1.f-wwi-wwa.x)*pA.x + wwi*ppa.x; if (ja+0==i) l=0.f; oA.x=l;
            f0+=pa0.x*l; f1+=pa1.x*l; f2+=pa2.x*l; f3+=pa3.x*l;
            bw0[0]+=pri0*l; bw1[0]+=pri1*l; bw2[0]+=pri2*l; bw3[0]+=pri3*l;
        }
        {
            float l = (1.f-wwi-wwa.y)*pA.y + wwi*ppa.y; if (ja+1==i) l=0.f; oA.y=l;
            f0+=pa0.y*l; f1+=pa1.y*l; f2+=pa2.y*l; f3+=pa3.y*l;
            bw0[1]+=pri0*l; bw1[1]+=pri1*l; bw2[1]+=pri2*l; bw3[1]+=pri3*l;
        }
        {
            float l = (1.f-wwi-wwa.z)*pA.z + wwi*ppa.z; if (ja+2==i) l=0.f; oA.z=l;
            f0+=pa0.z*l; f1+=pa1.z*l; f2+=pa2.z*l; f3+=pa3.z*l;
            bw0[2]+=pri0*l; bw1[2]+=pri1*l; bw2[2]+=pri2*l; bw3[2]+=pri3*l;
        }
        {
            float l = (1.f-wwi-wwa.w)*pA.w + wwi*ppa.w; if (ja+3==i) l=0.f; oA.w=l;
            f0+=pa0.w*l; f1+=pa1.w*l; f2+=pa2.w*l; f3+=pa3.w*l;
            bw0[3]+=pri0*l; bw1[3]+=pri1*l; bw2[3]+=pri2*l; bw3[3]+=pri3*l;
        }
        {
            float l = (1.f-wwi-wwb.x)*pB.x + wwi*ppb.x; if (jb+0==i) l=0.f; oB.x=l;
            f0+=pb0.x*l; f1+=pb1.x*l; f2+=pb2.x*l; f3+=pb3.x*l;
            bw0[4]+=pri0*l; bw1[4]+=pri1*l; bw2[4]+=pri2*l; bw3[4]+=pri3*l;
        }
        {
            float l = (1.f-wwi-wwb.y)*pB.y + wwi*ppb.y; if (jb+1==i) l=0.f; oB.y=l;
            f0+=pb0.y*l; f1+=pb1.y*l; f2+=pb2.y*l; f3+=pb3.y*l;
            bw0[5]+=pri0*l; bw1[5]+=pri1*l; bw2[5]+=pri2*l; bw3[5]+=pri3*l;
        }
        {
            float l = (1.f-wwi-wwb.z)*pB.z + wwi*ppb.z; if (jb+2==i) l=0.f; oB.z=l;
            f0+=pb0.z*l; f1+=pb1.z*l; f2+=pb2.z*l; f3+=pb3.z*l;
            bw0[6]+=pri0*l; bw1[6]+=pri1*l; bw2[6]+=pri2*l; bw3[6]+=pri3*l;
        }
        {
            float l = (1.f-wwi-wwb.w)*pB.w + wwi*ppb.w; if (jb+3==i) l=0.f; oB.w=l;
            f0+=pb0.w*l; f1+=pb1.w*l; f2+=pb2.w*l; f3+=pb3.w*l;
            bw0[7]+=pri0*l; bw1[7]+=pri1*l; bw2[7]+=pri2*l; bw3[7]+=pri3*l;
        }
        float4* lo = (float4*)(out_link + ((size_t)w*MM+i)*MM);
        __stcs(lo + tid, oA);
        __stcs(lo + 512 + tid, oB);
        float fv = gred4(f0,f1,f2,f3,lane);
        if ((lane&7)==0) s_fred[ii][lane>>3][wid]=fv;
    }
    __syncthreads();
    if (tid < LCHUNK*4){
        int row = tid>>2, r = tid&3;
        float s=0.f;
        #pragma unroll
        for (int k=0;k<16;k++) s += s_fred[row][r][k];
        g_fwd[(r*NWH + w)*MM + i0 + row] = s;
    }
    size_t pb = (size_t)(w*LNCH + chunk)*4;
    ((float4*)(g_part_bwd + (pb+0)*MM))[tid]     = make_float4(bw0[0],bw0[1],bw0[2],bw0[3]);
    ((float4*)(g_part_bwd + (pb+0)*MM))[512+tid] = make_float4(bw0[4],bw0[5],bw0[6],bw0[7]);
    ((float4*)(g_part_bwd + (pb+1)*MM))[tid]     = make_float4(bw1[0],bw1[1],bw1[2],bw1[3]);
    ((float4*)(g_part_bwd + (pb+1)*MM))[512+tid] = make_float4(bw1[4],bw1[5],bw1[6],bw1[7]);
    ((float4*)(g_part_bwd + (pb+2)*MM))[tid]     = make_float4(bw2[0],bw2[1],bw2[2],bw2[3]);
    ((float4*)(g_part_bwd + (pb+2)*MM))[512+tid] = make_float4(bw2[4],bw2[5],bw2[6],bw2[7]);
    ((float4*)(g_part_bwd + (pb+3)*MM))[tid]     = make_float4(bw3[0],bw3[1],bw3[2],bw3[3]);
    ((float4*)(g_part_bwd + (pb+3)*MM))[512+tid] = make_float4(bw3[4],bw3[5],bw3[6],bw3[7]);
}

// ------------- kernel 6: reduce bwd partials (fixed order, deterministic) --
__global__ void k_bwdreduce(){
    int idx = blockIdx.x*blockDim.x + threadIdx.x; // 32768
    if (idx >= RH*NWH*MM) return;
    int m = idx & (MM-1);
    int w = (idx >> 12) & 1;
    int r = idx >> 13;
    float s=0.f;
    #pragma unroll 8
    for (int t=0;t<LNCH;t++)
        s += g_part_bwd[((size_t)(w*LNCH+t)*4 + r)*MM + m];
    g_bwd[idx]=s;
}

// ------------- kernel 7: read weights — one block per read head -----------
__global__ void k_readw(float* __restrict__ out_rw){
    __shared__ float s_e[MM];
    __shared__ float red[32];
    __shared__ float s_bc;
    const int T = 1024;
    int tid=threadIdx.x, lane=tid&31, wid=tid>>5;
    int r = blockIdx.x;
    float kn=0.f;
    for (int d=tid;d<WORDD;d+=T){ float k=g_rk[r*WORDD+d]; kn+=k*k; }
    kn = wred(kn);
    if (lane==0) red[wid]=kn;
    __syncthreads();
    if (tid==0){ float s=0; for(int k=0;k<32;k++) s+=red[k]; s_bc=sqrtf(s);}
    __syncthreads();
    kn=s_bc;
    float rs = g_small[30+r];
    float mx=-3.4e38f;
    for (int m=tid;m<MM;m+=T){
        float l = g_rdot[r*MM+m]/(kn*g_newnorm[m])*rs;
        mx=fmaxf(mx,l);
    }
    #pragma unroll
    for (int o=16;o;o>>=1) mx=fmaxf(mx,__shfl_xor_sync(0xFFFFFFFFu,mx,o));
    if (lane==0) red[wid]=mx;
    __syncthreads();
    if (tid==0){ float s=-3.4e38f; for(int k=0;k<32;k++) s=fmaxf(s,red[k]); s_bc=s;}
    __syncthreads();
    mx=s_bc;
    float sume=0.f;
    for (int m=tid;m<MM;m+=T){
        float l = g_rdot[r*MM+m]/(kn*g_newnorm[m])*rs;
        float e = expf(l-mx);
        s_e[m]=e; sume+=e;
    }
    sume = wred(sume);
    if (lane==0) red[wid]=sume;
    __syncthreads();
    if (tid==0){ float s=0; for(int k=0;k<32;k++) s+=red[k]; s_bc=s;}
    __syncthreads();
    float inv = 1.f/s_bc;
    float bm0=g_small[8+r*5+0], bm1=g_small[8+r*5+1];
    float fm0=g_small[8+r*5+2], fm1=g_small[8+r*5+3];
    float cm =g_small[8+r*5+4];
    for (int m=tid;m<MM;m+=T){
        float v = bm0*g_bwd[(r*2+0)*MM+m] + bm1*g_bwd[(r*2+1)*MM+m]
                + fm0*g_fwd[(r*2+0)*MM+m] + fm1*g_fwd[(r*2+1)*MM+m]
                + cm*s_e[m]*inv;
        g_rw[r*MM+m]=v; out_rw[r*MM+m]=v;
    }
}

// ------------- kernel 8: read_words partials -------------------------------
__global__ void k_readwords(const float* __restrict__ nm){
    __shared__ float s_rw[4][256];
    int d = blockIdx.x*256 + threadIdx.x;
    int m0 = blockIdx.y*256;
    #pragma unroll
    for (int r=0;r<4;r++) s_rw[r][threadIdx.x] = g_rw[r*MM + m0 + threadIdx.x];
    __syncthreads();
    float a0=0,a1=0,a2=0,a3=0;
    #pragma unroll 4
    for (int mm=0;mm<256;mm++){
        float v = nm[(size_t)(m0+mm)*WORDD + d];
        a0+=s_rw[0][mm]*v; a1+=s_rw[1][mm]*v; a2+=s_rw[2][mm]*v; a3+=s_rw[3][mm]*v;
    }
    g_part_rw[(blockIdx.y*4+0)*WORDD+d]=a0;
    g_part_rw[(blockIdx.y*4+1)*WORDD+d]=a1;
    g_part_rw[(blockIdx.y*4+2)*WORDD+d]=a2;
    g_part_rw[(blockIdx.y*4+3)*WORDD+d]=a3;
}

// ------------- kernel 9: reduce read_words partials ------------------------
__global__ void k_rwreduce(float* __restrict__ out_rwords){
    int idx = blockIdx.x*blockDim.x+threadIdx.x; // 16384
    if (idx >= RH*WORDD) return;
    int r = idx >> 12; int d = idx & (WORDD-1);
    float s=0.f;
    #pragma unroll
    for (int t=0;t<16;t++) s += g_part_rw[(t*4+r)*WORDD+d];
    out_rwords[idx]=s;
}

// ---------------------------------------------------------------------------
extern "C" void kernel_launch(void* const* d_in, const int* in_sizes, int n_in,
                              void* d_out, int out_size) {
    const float* x      = (const float*)d_in[0];
    const float* memory = (const float*)d_in[1];
    const float* prw    = (const float*)d_in[2];
    const float* pww    = (const float*)d_in[3];
    const float* plink  = (const float*)d_in[4];
    const float* pprec  = (const float*)d_in[5];
    const float* pusage = (const float*)d_in[6];

    float* out = (float*)d_out;
    float* o_rwords = out;                            // 4*4096
    float* o_nm     = out + 16384;                    // 4096*4096
    float* o_rw     = out + 16384 + 16777216;         // 4*4096
    float* o_ww     = o_rw + 16384;                   // 2*4096
    float* o_link   = o_ww + 8192;                    // 2*4096*4096
    float* o_prec   = o_link + 33554432;              // 2*4096
    float* o_usage  = o_prec + 8192;                  // 4096

    // R9-proven skeleton: single side stream, exactly two cross-stream events
    cudaStream_t s2;
    cudaStreamCreateWithFlags(&s2, cudaStreamNonBlocking);
    cudaEvent_t eS, eL;
    cudaEventCreateWithFlags(&eS, cudaEventDisableTiming);
    cudaEventCreateWithFlags(&eL, cudaEventDisableTiming);

    // 1. all linears
    {
        int warps = 40994;
        int blocks = (warps*32 + 255)/256;
        k_matvec<<<blocks, 256>>>(x,
            (const float*)d_in[7],  (const float*)d_in[8],
            (const float*)d_in[9],  (const float*)d_in[10],
            (const float*)d_in[11], (const float*)d_in[12],
            (const float*)d_in[13], (const float*)d_in[14],
            (const float*)d_in[15], (const float*)d_in[16],
            (const float*)d_in[17], (const float*)d_in[18],
            (const float*)d_in[19], (const float*)d_in[20],
            (const float*)d_in[21], (const float*)d_in[22],
            (const float*)d_in[23], (const float*)d_in[24],
            (const float*)d_in[25], (const float*)d_in[26]);
    }
    // 2. write-key similarity dot + mem norms (main, like R9)
    k_memdot<<<128, 1024>>>(memory);
    // 3. serial core: cw + rank/scan allocation chain (replaces bitonic k_small)
    k_cw<<<2, 1024>>>();
    k_usage<<<4, 1024>>>(prw, pww, pusage);
    k_rank<<<4, 1024>>>(0);
    k_scan<<<1, 1024>>>(0, o_usage);
    k_rank<<<4, 1024>>>(1);
    k_scan<<<1, 1024>>>(1, o_usage);
    k_wwprec<<<2, 1024>>>(pprec, o_ww, o_prec);
    cudaEventRecord(eS, 0);
    // 5. link on s2 (needs g_ww)
    cudaStreamWaitEvent(s2, eS, 0);
    k_link<<<dim3(LNCH,2), 512, 0, s2>>>(plink, pprec, prw, o_link);
    cudaEventRecord(eL, s2);
    // 4. newmem on main, concurrent with link
    k_newmem<<<128, 1024>>>(memory, o_nm);
    cudaStreamWaitEvent(0, eL, 0);
    // tail
    k_bwdreduce<<<128, 256>>>();
    k_readw<<<4, 1024>>>(o_rw);
    k_readwords<<<dim3(16,16), 256>>>(o_nm);
    k_rwreduce<<<64, 256>>>(o_rwords);
}

// round 14
// speedup vs baseline: 2.0330x; 2.0330x over previous
#include <cuda_runtime.h>
#include <math.h>

#define MM 4096
#define WORDD 4096
#define NWH 2
#define RH 4
#define EPSV 0.001f
#define LCHUNK 64
#define LNCH 64   // 4096 / LCHUNK

// ---------------- scratch (device globals; allocation-free) ----------------
__device__ __align__(16) float g_wv[NWH*WORDD];
__device__ __align__(16) float g_ev[NWH*WORDD];
__device__ __align__(16) float g_wk[NWH*WORDD];
__device__ __align__(16) float g_rk[RH*WORDD];
__device__ __align__(16) float g_small[64]; // fg[0..3] ag[4..5] wg[6..7] rm[8..27] ws[28..29] rs[30..33]
__device__ __align__(16) float g_dot[NWH*MM];
__device__ __align__(16) float g_memnorm[MM];
__device__ __align__(16) float g_cw[NWH*MM];
__device__ __align__(16) float g_alloc[NWH*MM];
__device__ __align__(16) float g_ww[NWH*MM];
__device__ __align__(16) float g_usageA[MM];
__device__ __align__(16) float g_usageB[MM];
__device__ __align__(16) float g_sortedu[MM];
__device__ __align__(16) int   g_rankidx[MM];
__device__ __align__(16) int   g_partcnt[32*MM];    // 512 KB partial rank counts
__device__ __align__(16) float g_rdot[RH*MM];
__device__ __align__(16) float g_newnorm[MM];
__device__ __align__(16) float g_fwd[RH*NWH*MM];
__device__ __align__(16) float g_bwd[RH*NWH*MM];
__device__ __align__(16) float g_rw[RH*MM];
__device__ __align__(16) float g_part_bwd[NWH*LNCH*RH*MM];  // 8 MB fixed-order partials
__device__ __align__(16) float g_part_rw[16*RH*WORDD];      // 1 MB

__device__ __forceinline__ float wred(float v){
    #pragma unroll
    for (int o=16;o;o>>=1) v += __shfl_xor_sync(0xFFFFFFFFu,v,o);
    return v;
}
__device__ __forceinline__ float gred4(float a, float b, float c, float d, int lane){
    float x1 = (lane&16)? a : c;
    float x2 = (lane&16)? b : d;
    float r1 = __shfl_xor_sync(0xFFFFFFFFu, x1, 16);
    float r2 = __shfl_xor_sync(0xFFFFFFFFu, x2, 16);
    float va = ((lane&16)? c : a) + r1;
    float vb = ((lane&16)? d : b) + r2;
    float y = (lane&8)? va : vb;
    float r = __shfl_xor_sync(0xFFFFFFFFu, y, 8);
    float v = ((lane&8)? vb : va) + r;
    #pragma unroll
    for (int o=4;o;o>>=1) v += __shfl_xor_sync(0xFFFFFFFFu, v, o);
    return v;
}
__device__ __forceinline__ float gred2(float a, float b, int lane){
    float x = (lane&16)? a : b;
    float r = __shfl_xor_sync(0xFFFFFFFFu, x, 16);
    float v = ((lane&16)? b : a) + r;
    #pragma unroll
    for (int o=8;o;o>>=1) v += __shfl_xor_sync(0xFFFFFFFFu, v, o);
    return v;
}

// ---------------- kernel 1: all linear layers (warp-per-row matvec) --------
__global__ void k_matvec(const float* __restrict__ x,
    const float* __restrict__ Wwv, const float* __restrict__ bwv,
    const float* __restrict__ Wev, const float* __restrict__ bev,
    const float* __restrict__ Wfg, const float* __restrict__ bfg,
    const float* __restrict__ Wag, const float* __restrict__ bag,
    const float* __restrict__ Wwg, const float* __restrict__ bwg,
    const float* __restrict__ Wrm, const float* __restrict__ brm,
    const float* __restrict__ Wwk, const float* __restrict__ bwk,
    const float* __restrict__ Wws, const float* __restrict__ bws,
    const float* __restrict__ Wrk, const float* __restrict__ brk,
    const float* __restrict__ Wrs, const float* __restrict__ brs)
{
    int warp = (blockIdx.x*blockDim.x + threadIdx.x) >> 5;
    int lane = threadIdx.x & 31;
    if (warp >= 40994) return;
    const float* W; const float* b; float* out; int row; int act;
    if (warp < 8192)       { W=Wwv; b=bwv; out=g_wv; row=warp;       act=0; }
    else if (warp < 16384) { W=Wev; b=bev; out=g_ev; row=warp-8192;  act=1; }
    else if (warp < 24576) { W=Wwk; b=bwk; out=g_wk; row=warp-16384; act=1; }
    else if (warp < 40960) { W=Wrk; b=brk; out=g_rk; row=warp-24576; act=0; }
    else {
        int r = warp - 40960;
        if (r < 4)       { W=Wfg; b=bfg; out=g_small+0;  row=r;    act=1; }
        else if (r < 6)  { W=Wag; b=bag; out=g_small+4;  row=r-4;  act=1; }
        else if (r < 8)  { W=Wwg; b=bwg; out=g_small+6;  row=r-6;  act=1; }
        else if (r < 28) { W=Wrm; b=brm; out=g_small+8;  row=r-8;  act=1; }
        else if (r < 30) { W=Wws; b=bws; out=g_small+28; row=r-28; act=0; }
        else             { W=Wrs; b=brs; out=g_small+30; row=r-30; act=0; }
    }
    const float4* Wr = (const float4*)(W + (size_t)row*1024);
    const float4* x4 = (const float4*)x;
    float s = 0.f;
    #pragma unroll 8
    for (int i = lane; i < 256; i += 32) {
        float4 w4 = Wr[i], xx = x4[i];
        s += w4.x*xx.x + w4.y*xx.y + w4.z*xx.z + w4.w*xx.w;
    }
    s = wred(s);
    if (lane==0) {
        s += b[row];
        if (act) s = 1.f/(1.f+expf(-s));
        out[row] = s;
    }
}

// ------------- kernel 2: dot(write_keys, memory) + memory row norms --------
__global__ void __launch_bounds__(1024) k_memdot(const float* __restrict__ memory) {
    __shared__ float s_part[32][3*32];
    int tid = threadIdx.x, lane = tid&31, wid = tid>>5;
    const float4* wk4 = (const float4*)g_wk;
    float4 k0 = __ldg(&wk4[tid]);
    float4 k1 = __ldg(&wk4[1024+tid]);
    int base = blockIdx.x*32;
    float4 vA_n = __ldg((const float4*)(memory + (size_t)base*WORDD) + tid);
    float4 vB_n = __ldg((const float4*)(memory + (size_t)(base+1)*WORDD) + tid);
    #pragma unroll 1
    for (int ii = 0; ii < 32; ii += 2) {
        float4 vA = vA_n, vB = vB_n;
        if (ii < 30) {
            vA_n = __ldg((const float4*)(memory + (size_t)(base+ii+2)*WORDD) + tid);
            vB_n = __ldg((const float4*)(memory + (size_t)(base+ii+3)*WORDD) + tid);
        }
        float dA0 = vA.x*k0.x+vA.y*k0.y+vA.z*k0.z+vA.w*k0.w;
        float dA1 = vA.x*k1.x+vA.y*k1.y+vA.z*k1.z+vA.w*k1.w;
        float nnA = vA.x*vA.x+vA.y*vA.y+vA.z*vA.z+vA.w*vA.w;
        float dB0 = vB.x*k0.x+vB.y*k0.y+vB.z*k0.z+vB.w*k0.w;
        float dB1 = vB.x*k1.x+vB.y*k1.y+vB.z*k1.z+vB.w*k1.w;
        float nnB = vB.x*vB.x+vB.y*vB.y+vB.z*vB.z+vB.w*vB.w;
        float dv = gred4(dA0,dA1,dB0,dB1,lane);
        float nv = gred2(nnA,nnB,lane);
        if (lane==0)  s_part[ii][wid]      = dv;
        if (lane==8)  s_part[ii][32+wid]   = dv;
        if (lane==16) s_part[ii+1][wid]    = dv;
        if (lane==24) s_part[ii+1][32+wid] = dv;
        if (lane==0)  s_part[ii][64+wid]   = nv;
        if (lane==16) s_part[ii+1][64+wid] = nv;
    }
    __syncthreads();
    if (tid < 96) {
        int row = tid/3, q = tid - row*3;
        float s = 0.f;
        #pragma unroll
        for (int k=0;k<32;k++) s += s_part[row][q*32+k];
        int m = base + row;
        if (q==0) g_dot[m]=s; else if (q==1) g_dot[MM+m]=s; else g_memnorm[m]=sqrtf(s);
    }
}

// ------------- kernel 3a: content weights (per write head, parallel) -------
__global__ void k_cw(){
    __shared__ float red[32];
    __shared__ float s_bc;
    const int T = 1024;
    int tid=threadIdx.x, lane=tid&31, wid=tid>>5;
    int head = blockIdx.x;
    float kn=0.f;
    for (int d=tid; d<WORDD; d+=T){ float k = g_wk[head*WORDD+d]; kn += k*k; }
    kn = wred(kn);
    if (lane==0) red[wid]=kn;
    __syncthreads();
    if (tid==0){ float s=0; for(int k=0;k<32;k++) s+=red[k]; s_bc = sqrtf(s);}
    __syncthreads();
    kn = s_bc;
    float ws = g_small[28+head];
    float beta = 1.f + log1pf(expf(ws));
    float mx = -3.4e38f;
    for (int m=tid;m<MM;m+=T){
        float l = g_dot[head*MM+m]/(kn*g_memnorm[m]+EPSV)*beta;
        mx = fmaxf(mx,l);
    }
    #pragma unroll
    for (int o=16;o;o>>=1) mx = fmaxf(mx,__shfl_xor_sync(0xFFFFFFFFu,mx,o));
    if (lane==0) red[wid]=mx;
    __syncthreads();
    if (tid==0){ float s=-3.4e38f; for(int k=0;k<32;k++) s=fmaxf(s,red[k]); s_bc=s;}
    __syncthreads();
    mx = s_bc;
    float sume=0.f;
    for (int m=tid;m<MM;m+=T){
        float l = g_dot[head*MM+m]/(kn*g_memnorm[m]+EPSV)*beta;
        float e = expf(l-mx);
        g_cw[head*MM+m]=e; sume+=e;
    }
    sume = wred(sume);
    if (lane==0) red[wid]=sume;
    __syncthreads();
    if (tid==0){ float s=0; for(int k=0;k<32;k++) s+=red[k]; s_bc=s;}
    __syncthreads();
    float inv = 1.f/s_bc;
    for (int m=tid;m<MM;m+=T) g_cw[head*MM+m] *= inv;
}

// ------------- kernel 3b: initial usage ------------------------------------
__global__ void k_usage(const float* __restrict__ prev_rw,
                        const float* __restrict__ prev_ww,
                        const float* __restrict__ prev_usage){
    int m = blockIdx.x*1024 + threadIdx.x;
    float fg0=g_small[0],fg1=g_small[1],fg2=g_small[2],fg3=g_small[3];
    float u = prev_usage[m];
    u = u + (1.f-u)*(1.f - prev_ww[m]*prev_ww[MM+m]);
    float p = (fg0*prev_rw[m])*(fg1*prev_rw[MM+m])*(fg2*prev_rw[2*MM+m])*(fg3*prev_rw[3*MM+m]);
    g_usageA[m] = u*(1.f - p);
}

// ------------- kernel 3c: partial rank counts (grid 4 x 32, no atomics) ----
// block (bi,bj): 128-key slice bj in smem (packed u64), each thread counts
// its element m=bi*1024+tid against the slice. Deterministic fixed-slot out.
__global__ void __launch_bounds__(1024) k_rankpart(int which){
    __shared__ unsigned long long s_k[128];
    const float* usage_in = which ? g_usageB : g_usageA;
    int tid = threadIdx.x;
    int bj = blockIdx.y;
    if (tid < 128){
        int j = bj*128 + tid;
        float u = EPSV + (1.f-EPSV)*usage_in[j];
        s_k[tid] = ((unsigned long long)__float_as_uint(u) << 32) | (unsigned)j;
    }
    __syncthreads();
    int m = blockIdx.x*1024 + tid;
    float um = EPSV + (1.f-EPSV)*usage_in[m];
    unsigned long long km = ((unsigned long long)__float_as_uint(um) << 32) | (unsigned)m;
    int cnt = 0;
    #pragma unroll
    for (int j=0;j<128;j++) cnt += (s_k[j] < km);
    g_partcnt[bj*MM + m] = cnt;
}

// ------------- kernel 3c2: sum partials + scatter sorted key ---------------
__global__ void __launch_bounds__(1024) k_scatter(int which){
    const float* usage_in = which ? g_usageB : g_usageA;
    int m = blockIdx.x*1024 + threadIdx.x;
    int cnt = 0;
    #pragma unroll
    for (int c=0;c<32;c++) cnt += g_partcnt[c*MM + m];
    float um = EPSV + (1.f-EPSV)*usage_in[m];
    g_sortedu[cnt] = um;
    g_rankidx[m] = cnt;
}

// ------------- kernel 3d: cumprod scan over sorted u + alloc + usage upd ---
__global__ void __launch_bounds__(1024) k_scan(int head,
                                               float* __restrict__ out_usage_final){
    __shared__ float s_alloc[MM];
    __shared__ float s_wsum2[32];
    __shared__ float s_wpre[32];
    const float* usage_in = head ? g_usageB : g_usageA;
    int tid=threadIdx.x, lane=tid&31, wid=tid>>5;
    int base = tid*4;
    float4 xv = *(const float4*)(g_sortedu + base);
    float x0=xv.x, x1=xv.y, x2=xv.z, x3=xv.w;
    float c0=x0, c1=c0*x1, c2=c1*x2, c3=c2*x3;
    float t3=c3;
    #pragma unroll
    for (int o=1;o<32;o<<=1){ float n=__shfl_up_sync(0xFFFFFFFFu,t3,o); if (lane>=o) t3*=n; }
    float warpExcl = __shfl_up_sync(0xFFFFFFFFu,t3,1); if (lane==0) warpExcl=1.f;
    if (lane==31) s_wsum2[wid]=t3;
    __syncthreads();
    if (tid<32){
        float w = s_wsum2[tid];
        float tw=w;
        #pragma unroll
        for (int o=1;o<32;o<<=1){ float n=__shfl_up_sync(0xFFFFFFFFu,tw,o); if (tid>=o) tw*=n; }
        float excl = __shfl_up_sync(0xFFFFFFFFu,tw,1); if (tid==0) excl=1.f;
        s_wpre[tid]=excl;
    }
    __syncthreads();
    float pre = s_wpre[wid]*warpExcl;
    s_alloc[base+0]=(1.f-x0)*pre;
    s_alloc[base+1]=(1.f-x1)*pre*c0;
    s_alloc[base+2]=(1.f-x2)*pre*c1;
    s_alloc[base+3]=(1.f-x3)*pre*c2;
    __syncthreads();
    float ag=g_small[4+head], wg=g_small[6+head];
    float agwg = ag*wg;
    for (int m=tid;m<MM;m+=1024){
        float a = s_alloc[g_rankidx[m]];
        g_alloc[head*MM+m] = a;
        float u = usage_in[m];
        float nu = u + (1.f - u)*agwg*a;
        if (head==0) g_usageB[m] = nu; else out_usage_final[m] = nu;
    }
}

// ------------- kernel 3e: write weights + precedence (per head) ------------
__global__ void k_wwprec(const float* __restrict__ prev_prec,
                         float* __restrict__ out_ww,
                         float* __restrict__ out_prec)
{
    __shared__ float red[32];
    __shared__ float s_bc;
    const int T = 1024;
    int tid=threadIdx.x, lane=tid&31, wid=tid>>5;
    int head = blockIdx.x;
    float ag = g_small[4+head], wg = g_small[6+head];
    float wsum = 0.f;
    for (int m=tid;m<MM;m+=T){
        float a = g_alloc[head*MM+m];
        float cw = g_cw[head*MM+m];
        float w = wg*(ag*a + (1.f-ag)*cw);
        g_ww[head*MM+m] = w;
        out_ww[head*MM+m] = w;
        wsum += w;
    }
    wsum = wred(wsum);
    if (lane==0) red[wid]=wsum;
    __syncthreads();
    if (tid==0){ float s=0; for(int k=0;k<32;k++) s+=red[k]; s_bc=s;}
    __syncthreads();
    float oms = 1.f - s_bc;
    for (int m=tid;m<MM;m+=T)
        out_prec[head*MM+m] = oms*prev_prec[head*MM+m] + g_ww[head*MM+m];
}

// ------------- kernel 4: new_memory + fused rdot + new norms ---------------
__global__ void __launch_bounds__(1024) k_newmem(const float* __restrict__ memory,
                                                 float* __restrict__ out_nm){
    __shared__ float s_part[32][5*32];
    int tid=threadIdx.x, lane=tid&31, wid=tid>>5;
    const float4* ev4=(const float4*)g_ev;
    const float4* wv4=(const float4*)g_wv;
    const float4* rk4=(const float4*)g_rk;
    float4 e0=__ldg(&ev4[tid]),      e1=__ldg(&ev4[1024+tid]);
    float4 a0=__ldg(&wv4[tid]),      a1=__ldg(&wv4[1024+tid]);
    float4 k0=__ldg(&rk4[tid]),      k1=__ldg(&rk4[1024+tid]);
    float4 k2=__ldg(&rk4[2048+tid]), k3=__ldg(&rk4[3072+tid]);
    int base = blockIdx.x*32;
    float4 v_next = __ldg((const float4*)(memory+(size_t)base*WORDD) + tid);
    #pragma unroll 1
    for (int ii=0; ii<32; ii++){
        int m = base+ii;
        float4 v = v_next;
        if (ii<31) v_next = __ldg((const float4*)(memory+(size_t)(m+1)*WORDD) + tid);
        float w0=__ldg(&g_ww[m]), w1=__ldg(&g_ww[MM+m]);
        float4 o;
        o.x = v.x*((1.f-w0*e0.x)*(1.f-w1*e1.x)) + w0*a0.x + w1*a1.x;
        o.y = v.y*((1.f-w0*e0.y)*(1.f-w1*e1.y)) + w0*a0.y + w1*a1.y;
        o.z = v.z*((1.f-w0*e0.z)*(1.f-w1*e1.z)) + w0*a0.z + w1*a1.z;
        o.w = v.w*((1.f-w0*e0.w)*(1.f-w1*e1.w)) + w0*a0.w + w1*a1.w;
        ((float4*)(out_nm+(size_t)m*WORDD))[tid]=o;
        float r0 = o.x*k0.x+o.y*k0.y+o.z*k0.z+o.w*k0.w;
        float r1 = o.x*k1.x+o.y*k1.y+o.z*k1.z+o.w*k1.w;
        float r2 = o.x*k2.x+o.y*k2.y+o.z*k2.z+o.w*k2.w;
        float r3 = o.x*k3.x+o.y*k3.y+o.z*k3.z+o.w*k3.w;
        float nn = o.x*o.x+o.y*o.y+o.z*o.z+o.w*o.w;
        float rv = gred4(r0,r1,r2,r3,lane);
        float nv = wred(nn);
        if ((lane&7)==0) s_part[ii][(lane>>3)*32+wid] = rv;
        if (lane==0)     s_part[ii][128+wid] = nv;
    }
    __syncthreads();
    if (tid < 160){
        int row=tid/5, q=tid-row*5;
        float s=0.f;
        #pragma unroll
        for (int k=0;k<32;k++) s += s_part[row][q*32+k];
        int m = base + row;
        if (q<4) g_rdot[q*MM+m]=s; else g_newnorm[m]=sqrtf(s);
    }
}

// ------------- kernel 5: link update + fused fwd_w/bwd_w -------------------
__global__ void __launch_bounds__(512) k_link(const float* __restrict__ prev_link,
                       const float* __restrict__ prev_prec,
                       const float* __restrict__ prev_rw,
                       float* __restrict__ out_link){
    __shared__ float s_fred[LCHUNK][4][16];
    int w = blockIdx.y;
    int chunk = blockIdx.x;
    int i0 = chunk*LCHUNK;
    int tid=threadIdx.x, lane=tid&31, wid=tid>>5;
    const float4* ww4 = (const float4*)(g_ww + w*MM);
    const float4* pp4 = (const float4*)(prev_prec + w*MM);
    const float4* pr4 = (const float4*)prev_rw;
    float4 wwa=__ldg(&ww4[tid]),       wwb=__ldg(&ww4[512+tid]);
    float4 ppa=__ldg(&pp4[tid]),       ppb=__ldg(&pp4[512+tid]);
    float4 pa0=__ldg(&pr4[tid]),       pb0=__ldg(&pr4[512+tid]);
    float4 pa1=__ldg(&pr4[1024+tid]),  pb1=__ldg(&pr4[1536+tid]);
    float4 pa2=__ldg(&pr4[2048+tid]),  pb2=__ldg(&pr4[2560+tid]);
    float4 pa3=__ldg(&pr4[3072+tid]),  pb3=__ldg(&pr4[3584+tid]);
    float bw0[8],bw1[8],bw2[8],bw3[8];
    #pragma unroll
    for (int c=0;c<8;c++){ bw0[c]=0.f;bw1[c]=0.f;bw2[c]=0.f;bw3[c]=0.f; }
    int ja = tid*4, jb = (512+tid)*4;
    const float4* plbase = (const float4*)(prev_link + (size_t)w*MM*MM);
    float4 pA_n = __ldcs(plbase + (size_t)i0*1024 + tid);
    float4 pB_n = __ldcs(plbase + (size_t)i0*1024 + 512 + tid);
    #pragma unroll 1
    for (int ii=0; ii<LCHUNK; ii++){
        int i = i0+ii;
        float4 pA = pA_n, pB = pB_n;
        if (ii<LCHUNK-1){
            pA_n = __ldcs(plbase + (size_t)(i+1)*1024 + tid);
            pB_n = __ldcs(plbase + (size_t)(i+1)*1024 + 512 + tid);
        }
        float wwi = __ldg(&g_ww[w*MM+i]);
        float pri0=__ldg(&prev_rw[i]),      pri1=__ldg(&prev_rw[MM+i]);
        float pri2=__ldg(&prev_rw[2*MM+i]), pri3=__ldg(&prev_rw[3*MM+i]);
        float f0=0.f,f1=0.f,f2=0.f,f3=0.f;
        float4 oA, oB;
        {
            float l = (1.f-wwi-wwa.x)*pA.x + wwi*ppa.x; if (ja+0==i) l=0.f; oA.x=l;
            f0+=pa0.x*l; f1+=pa1.x*l; f2+=pa2.x*l; f3+=pa3.x*l;
            bw0[0]+=pri0*l; bw1[0]+=pri1*l; bw2[0]+=pri2*l; bw3[0]+=pri3*l;
        }
        {
            float l = (1.f-wwi-wwa.y)*pA.y + wwi*ppa.y; if (ja+1==i) l=0.f; oA.y=l;
            f0+=pa0.y*l; f1+=pa1.y*l; f2+=pa2.y*l; f3+=pa3.y*l;
            bw0[1]+=pri0*l; bw1[1]+=pri1*l; bw2[1]+=pri2*l; bw3[1]+=pri3*l;
        }
        {
            float l = (1.f-wwi-wwa.z)*pA.z + wwi*ppa.z; if (ja+2==i) l=0.f; oA.z=l;
            f0+=pa0.z*l; f1+=pa1.z*l; f2+=pa2.z*l; f3+=pa3.z*l;
            bw0[2]+=pri0*l; bw1[2]+=pri1*l; bw2[2]+=pri2*l; bw3[2]+=pri3*l;
        }
        {
            float l = (1.f-wwi-wwa.w)*pA.w + wwi*ppa.w; if (ja+3==i) l=0.f; oA.w=l;
            f0+=pa0.w*l; f1+=pa1.w*l; f2+=pa2.w*l; f3+=pa3.w*l;
            bw0[3]+=pri0*l; bw1[3]+=pri1*l; bw2[3]+=pri2*l; bw3[3]+=pri3*l;
        }
        {
            float l = (1.f-wwi-wwb.x)*pB.x + wwi*ppb.x; if (jb+0==i) l=0.f; oB.x=l;
            f0+=pb0.x*l; f1+=pb1.x*l; f2+=pb2.x*l; f3+=pb3.x*l;
            bw0[4]+=pri0*l; bw1[4]+=pri1*l; bw2[4]+=pri2*l; bw3[4]+=pri3*l;
        }
        {
            float l = (1.f-wwi-wwb.y)*pB.y + wwi*ppb.y; if (jb+1==i) l=0.f; oB.y=l;
            f0+=pb0.y*l; f1+=pb1.y*l; f2+=pb2.y*l; f3+=pb3.y*l;
            bw0[5]+=pri0*l; bw1[5]+=pri1*l; bw2[5]+=pri2*l; bw3[5]+=pri3*l;
        }
        {
            float l = (1.f-wwi-wwb.z)*pB.z + wwi*ppb.z; if (jb+2==i) l=0.f; oB.z=l;
            f0+=pb0.z*l; f1+=pb1.z*l; f2+=pb2.z*l; f3+=pb3.z*l;
            bw0[6]+=pri0*l; bw1[6]+=pri1*l; bw2[6]+=pri2*l; bw3[6]+=pri3*l;
        }
        {
            float l = (1.f-wwi-wwb.w)*pB.w + wwi*ppb.w; if (jb+3==i) l=0.f; oB.w=l;
            f0+=pb0.w*l; f1+=pb1.w*l; f2+=pb2.w*l; f3+=pb3.w*l;
            bw0[7]+=pri0*l; bw1[7]+=pri1*l; bw2[7]+=pri2*l; bw3[7]+=pri3*l;
        }
        float4* lo = (float4*)(out_link + ((size_t)w*MM+i)*MM);
        __stcs(lo + tid, oA);
        __stcs(lo + 512 + tid, oB);
        float fv = gred4(f0,f1,f2,f3,lane);
        if ((lane&7)==0) s_fred[ii][lane>>3][wid]=fv;
    }
    __syncthreads();
    if (tid < LCHUNK*4){
        int row = tid>>2, r = tid&3;
        float s=0.f;
        #pragma unroll
        for (int k=0;k<16;k++) s += s_fred[row][r][k];
        g_fwd[(r*NWH + w)*MM + i0 + row] = s;
    }
    size_t pb = (size_t)(w*LNCH + chunk)*4;
    ((float4*)(g_part_bwd + (pb+0)*MM))[tid]     = make_float4(bw0[0],bw0[1],bw0[2],bw0[3]);
    ((float4*)(g_part_bwd + (pb+0)*MM))[512+tid] = make_float4(bw0[4],bw0[5],bw0[6],bw0[7]);
    ((float4*)(g_part_bwd + (pb+1)*MM))[tid]     = make_float4(bw1[0],bw1[1],bw1[2],bw1[3]);
    ((float4*)(g_part_bwd + (pb+1)*MM))[512+tid] = make_float4(bw1[4],bw1[5],bw1[6],bw1[7]);
    ((float4*)(g_part_bwd + (pb+2)*MM))[tid]     = make_float4(bw2[0],bw2[1],bw2[2],bw2[3]);
    ((float4*)(g_part_bwd + (pb+2)*MM))[512+tid] = make_float4(bw2[4],bw2[5],bw2[6],bw2[7]);
    ((float4*)(g_part_bwd + (pb+3)*MM))[tid]     = make_float4(bw3[0],bw3[1],bw3[2],bw3[3]);
    ((float4*)(g_part_bwd + (pb+3)*MM))[512+tid] = make_float4(bw3[4],bw3[5],bw3[6],bw3[7]);
}

// ------------- kernel 6: reduce bwd partials (fixed order, deterministic) --
__global__ void k_bwdreduce(){
    int idx = blockIdx.x*blockDim.x + threadIdx.x; // 32768
    if (idx >= RH*NWH*MM) return;
    int m = idx & (MM-1);
    int w = (idx >> 12) & 1;
    int r = idx >> 13;
    float s=0.f;
    #pragma unroll 8
    for (int t=0;t<LNCH;t++)
        s += g_part_bwd[((size_t)(w*LNCH+t)*4 + r)*MM + m];
    g_bwd[idx]=s;
}

// ------------- kernel 7: read weights — one block per read head -----------
__global__ void k_readw(float* __restrict__ out_rw){
    __shared__ float s_e[MM];
    __shared__ float red[32];
    __shared__ float s_bc;
    const int T = 1024;
    int tid=threadIdx.x, lane=tid&31, wid=tid>>5;
    int r = blockIdx.x;
    float kn=0.f;
    for (int d=tid;d<WORDD;d+=T){ float k=g_rk[r*WORDD+d]; kn+=k*k; }
    kn = wred(kn);
    if (lane==0) red[wid]=kn;
    __syncthreads();
    if (tid==0){ float s=0; for(int k=0;k<32;k++) s+=red[k]; s_bc=sqrtf(s);}
    __syncthreads();
    kn=s_bc;
    float rs = g_small[30+r];
    float mx=-3.4e38f;
    for (int m=tid;m<MM;m+=T){
        float l = g_rdot[r*MM+m]/(kn*g_newnorm[m])*rs;
        mx=fmaxf(mx,l);
    }
    #pragma unroll
    for (int o=16;o;o>>=1) mx=fmaxf(mx,__shfl_xor_sync(0xFFFFFFFFu,mx,o));
    if (lane==0) red[wid]=mx;
    __syncthreads();
    if (tid==0){ float s=-3.4e38f; for(int k=0;k<32;k++) s=fmaxf(s,red[k]); s_bc=s;}
    __syncthreads();
    mx=s_bc;
    float sume=0.f;
    for (int m=tid;m<MM;m+=T){
        float l = g_rdot[r*MM+m]/(kn*g_newnorm[m])*rs;
        float e = expf(l-mx);
        s_e[m]=e; sume+=e;
    }
    sume = wred(sume);
    if (lane==0) red[wid]=sume;
    __syncthreads();
    if (tid==0){ float s=0; for(int k=0;k<32;k++) s+=red[k]; s_bc=s;}
    __syncthreads();
    float inv = 1.f/s_bc;
    float bm0=g_small[8+r*5+0], bm1=g_small[8+r*5+1];
    float fm0=g_small[8+r*5+2], fm1=g_small[8+r*5+3];
    float cm =g_small[8+r*5+4];
    for (int m=tid;m<MM;m+=T){
        float v = bm0*g_bwd[(r*2+0)*MM+m] + bm1*g_bwd[(r*2+1)*MM+m]
                + fm0*g_fwd[(r*2+0)*MM+m] + fm1*g_fwd[(r*2+1)*MM+m]
                + cm*s_e[m]*inv;
        g_rw[r*MM+m]=v; out_rw[r*MM+m]=v;
    }
}

// ------------- kernel 8: read_words partials -------------------------------
__global__ void k_readwords(const float* __restrict__ nm){
    __shared__ float s_rw[4][256];
    int d = blockIdx.x*256 + threadIdx.x;
    int m0 = blockIdx.y*256;
    #pragma unroll
    for (int r=0;r<4;r++) s_rw[r][threadIdx.x] = g_rw[r*MM + m0 + threadIdx.x];
    __syncthreads();
    float a0=0,a1=0,a2=0,a3=0;
    #pragma unroll 4
    for (int mm=0;mm<256;mm++){
        float v = nm[(size_t)(m0+mm)*WORDD + d];
        a0+=s_rw[0][mm]*v; a1+=s_rw[1][mm]*v; a2+=s_rw[2][mm]*v; a3+=s_rw[3][mm]*v;
    }
    g_part_rw[(blockIdx.y*4+0)*WORDD+d]=a0;
    g_part_rw[(blockIdx.y*4+1)*WORDD+d]=a1;
    g_part_rw[(blockIdx.y*4+2)*WORDD+d]=a2;
    g_part_rw[(blockIdx.y*4+3)*WORDD+d]=a3;
}

// ------------- kernel 9: reduce read_words partials ------------------------
__global__ void k_rwreduce(float* __restrict__ out_rwords){
    int idx = blockIdx.x*blockDim.x+threadIdx.x; // 16384
    if (idx >= RH*WORDD) return;
    int r = idx >> 12; int d = idx & (WORDD-1);
    float s=0.f;
    #pragma unroll
    for (int t=0;t<16;t++) s += g_part_rw[(t*4+r)*WORDD+d];
    out_rwords[idx]=s;
}

// ---------------------------------------------------------------------------
extern "C" void kernel_launch(void* const* d_in, const int* in_sizes, int n_in,
                              void* d_out, int out_size) {
    const float* x      = (const float*)d_in[0];
    const float* memory = (const float*)d_in[1];
    const float* prw    = (const float*)d_in[2];
    const float* pww    = (const float*)d_in[3];
    const float* plink  = (const float*)d_in[4];
    const float* pprec  = (const float*)d_in[5];
    const float* pusage = (const float*)d_in[6];

    float* out = (float*)d_out;
    float* o_rwords = out;                            // 4*4096
    float* o_nm     = out + 16384;                    // 4096*4096
    float* o_rw     = out + 16384 + 16777216;         // 4*4096
    float* o_ww     = o_rw + 16384;                   // 2*4096
    float* o_link   = o_ww + 8192;                    // 2*4096*4096
    float* o_prec   = o_link + 33554432;              // 2*4096
    float* o_usage  = o_prec + 8192;                  // 4096

    // R9-proven skeleton: single side stream, exactly two cross-stream events
    cudaStream_t s2;
    cudaStreamCreateWithFlags(&s2, cudaStreamNonBlocking);
    cudaEvent_t eS, eL;
    cudaEventCreateWithFlags(&eS, cudaEventDisableTiming);
    cudaEventCreateWithFlags(&eL, cudaEventDisableTiming);

    // 1. all linears
    {
        int warps = 40994;
        int blocks = (warps*32 + 255)/256;
        k_matvec<<<blocks, 256>>>(x,
            (const float*)d_in[7],  (const float*)d_in[8],
            (const float*)d_in[9],  (const float*)d_in[10],
            (const float*)d_in[11], (const float*)d_in[12],
            (const float*)d_in[13], (const float*)d_in[14],
            (const float*)d_in[15], (const float*)d_in[16],
            (const float*)d_in[17], (const float*)d_in[18],
            (const float*)d_in[19], (const float*)d_in[20],
            (const float*)d_in[21], (const float*)d_in[22],
            (const float*)d_in[23], (const float*)d_in[24],
            (const float*)d_in[25], (const float*)d_in[26]);
    }
    // 2. write-key similarity dot + mem norms
    k_memdot<<<128, 1024>>>(memory);
    // 3. serial core: cw + (rankpart/scatter/scan) x 2 heads + wwprec
    k_cw<<<2, 1024>>>();
    k_usage<<<4, 1024>>>(prw, pww, pusage);
    k_rankpart<<<dim3(4,32), 1024>>>(0);
    k_scatter<<<4, 1024>>>(0);
    k_scan<<<1, 1024>>>(0, o_usage);
    k_rankpart<<<dim3(4,32), 1024>>>(1);
    k_scatter<<<4, 1024>>>(1);
    k_scan<<<1, 1024>>>(1, o_usage);
    k_wwprec<<<2, 1024>>>(pprec, o_ww, o_prec);
    cudaEventRecord(eS, 0);
    // 5. link on s2 (needs g_ww)
    cudaStreamWaitEvent(s2, eS, 0);
    k_link<<<dim3(LNCH,2), 512, 0, s2>>>(plink, pprec, prw, o_link);
    cudaEventRecord(eL, s2);
    // 4. newmem on main, concurrent with link
    k_newmem<<<128, 1024>>>(memory, o_nm);
    cudaStreamWaitEvent(0, eL, 0);
    // tail
    k_bwdreduce<<<128, 256>>>();
    k_readw<<<4, 1024>>>(o_rw);
    k_readwords<<<dim3(16,16), 256>>>(o_nm);
    k_rwreduce<<<64, 256>>>(o_rwords);
}

// round 15
// speedup vs baseline: 2.2819x; 1.1225x over previous
#include <cuda_runtime.h>
#include <math.h>

#define MM 4096
#define WORDD 4096
#define NWH 2
#define RH 4
#define EPSV 0.001f
#define LCHUNK 64
#define LNCH 64   // 4096 / LCHUNK

// ---------------- scratch (device globals; allocation-free) ----------------
__device__ __align__(16) float g_wv[NWH*WORDD];
__device__ __align__(16) float g_ev[NWH*WORDD];
__device__ __align__(16) float g_wk[NWH*WORDD];
__device__ __align__(16) float g_rk[RH*WORDD];
__device__ __align__(16) float g_small[64]; // fg[0..3] ag[4..5] wg[6..7] rm[8..27] ws[28..29] rs[30..33]
__device__ __align__(16) float g_dot[NWH*MM];
__device__ __align__(16) float g_memnorm[MM];
__device__ __align__(16) float g_cw[NWH*MM];
__device__ __align__(16) float g_alloc[NWH*MM];
__device__ __align__(16) float g_ww[NWH*MM];
__device__ __align__(16) float g_usageA[MM];
__device__ __align__(16) float g_usageB[MM];
__device__ __align__(16) float g_sortedu[MM];
__device__ __align__(16) int   g_rankidx[MM];
__device__ __align__(16) int   g_partcnt[32*MM];    // 512 KB partial rank counts
__device__ __align__(16) float g_rdot[RH*MM];
__device__ __align__(16) float g_newnorm[MM];
__device__ __align__(16) float g_fwd[RH*NWH*MM];
__device__ __align__(16) float g_bwd[RH*NWH*MM];
__device__ __align__(16) float g_rw[RH*MM];
__device__ __align__(16) float g_part_bwd[NWH*LNCH*RH*MM];  // 8 MB fixed-order partials
__device__ __align__(16) float g_part_rw[16*RH*WORDD];      // 1 MB

__device__ __forceinline__ float wred(float v){
    #pragma unroll
    for (int o=16;o;o>>=1) v += __shfl_xor_sync(0xFFFFFFFFu,v,o);
    return v;
}
__device__ __forceinline__ float gred4(float a, float b, float c, float d, int lane){
    float x1 = (lane&16)? a : c;
    float x2 = (lane&16)? b : d;
    float r1 = __shfl_xor_sync(0xFFFFFFFFu, x1, 16);
    float r2 = __shfl_xor_sync(0xFFFFFFFFu, x2, 16);
    float va = ((lane&16)? c : a) + r1;
    float vb = ((lane&16)? d : b) + r2;
    float y = (lane&8)? va : vb;
    float r = __shfl_xor_sync(0xFFFFFFFFu, y, 8);
    float v = ((lane&8)? vb : va) + r;
    #pragma unroll
    for (int o=4;o;o>>=1) v += __shfl_xor_sync(0xFFFFFFFFu, v, o);
    return v;
}
__device__ __forceinline__ float gred2(float a, float b, int lane){
    float x = (lane&16)? a : b;
    float r = __shfl_xor_sync(0xFFFFFFFFu, x, 16);
    float v = ((lane&16)? b : a) + r;
    #pragma unroll
    for (int o=8;o;o>>=1) v += __shfl_xor_sync(0xFFFFFFFFu, v, o);
    return v;
}

// ---------------- kernel 1: all linear layers (warp-per-row matvec) --------
__global__ void k_matvec(const float* __restrict__ x,
    const float* __restrict__ Wwv, const float* __restrict__ bwv,
    const float* __restrict__ Wev, const float* __restrict__ bev,
    const float* __restrict__ Wfg, const float* __restrict__ bfg,
    const float* __restrict__ Wag, const float* __restrict__ bag,
    const float* __restrict__ Wwg, const float* __restrict__ bwg,
    const float* __restrict__ Wrm, const float* __restrict__ brm,
    const float* __restrict__ Wwk, const float* __restrict__ bwk,
    const float* __restrict__ Wws, const float* __restrict__ bws,
    const float* __restrict__ Wrk, const float* __restrict__ brk,
    const float* __restrict__ Wrs, const float* __restrict__ brs)
{
    int warp = (blockIdx.x*blockDim.x + threadIdx.x) >> 5;
    int lane = threadIdx.x & 31;
    if (warp >= 40994) return;
    const float* W; const float* b; float* out; int row; int act;
    if (warp < 8192)       { W=Wwv; b=bwv; out=g_wv; row=warp;       act=0; }
    else if (warp < 16384) { W=Wev; b=bev; out=g_ev; row=warp-8192;  act=1; }
    else if (warp < 24576) { W=Wwk; b=bwk; out=g_wk; row=warp-16384; act=1; }
    else if (warp < 40960) { W=Wrk; b=brk; out=g_rk; row=warp-24576; act=0; }
    else {
        int r = warp - 40960;
        if (r < 4)       { W=Wfg; b=bfg; out=g_small+0;  row=r;    act=1; }
        else if (r < 6)  { W=Wag; b=bag; out=g_small+4;  row=r-4;  act=1; }
        else if (r < 8)  { W=Wwg; b=bwg; out=g_small+6;  row=r-6;  act=1; }
        else if (r < 28) { W=Wrm; b=brm; out=g_small+8;  row=r-8;  act=1; }
        else if (r < 30) { W=Wws; b=bws; out=g_small+28; row=r-28; act=0; }
        else             { W=Wrs; b=brs; out=g_small+30; row=r-30; act=0; }
    }
    const float4* Wr = (const float4*)(W + (size_t)row*1024);
    const float4* x4 = (const float4*)x;
    float s = 0.f;
    #pragma unroll 8
    for (int i = lane; i < 256; i += 32) {
        float4 w4 = Wr[i], xx = x4[i];
        s += w4.x*xx.x + w4.y*xx.y + w4.z*xx.z + w4.w*xx.w;
    }
    s = wred(s);
    if (lane==0) {
        s += b[row];
        if (act) s = 1.f/(1.f+expf(-s));
        out[row] = s;
    }
}

// ------------- kernel 2: dot(write_keys, memory) + memory row norms --------
__global__ void __launch_bounds__(1024) k_memdot(const float* __restrict__ memory) {
    __shared__ float s_part[32][3*32];
    int tid = threadIdx.x, lane = tid&31, wid = tid>>5;
    const float4* wk4 = (const float4*)g_wk;
    float4 k0 = __ldg(&wk4[tid]);
    float4 k1 = __ldg(&wk4[1024+tid]);
    int base = blockIdx.x*32;
    float4 vA_n = __ldg((const float4*)(memory + (size_t)base*WORDD) + tid);
    float4 vB_n = __ldg((const float4*)(memory + (size_t)(base+1)*WORDD) + tid);
    #pragma unroll 1
    for (int ii = 0; ii < 32; ii += 2) {
        float4 vA = vA_n, vB = vB_n;
        if (ii < 30) {
            vA_n = __ldg((const float4*)(memory + (size_t)(base+ii+2)*WORDD) + tid);
            vB_n = __ldg((const float4*)(memory + (size_t)(base+ii+3)*WORDD) + tid);
        }
        float dA0 = vA.x*k0.x+vA.y*k0.y+vA.z*k0.z+vA.w*k0.w;
        float dA1 = vA.x*k1.x+vA.y*k1.y+vA.z*k1.z+vA.w*k1.w;
        float nnA = vA.x*vA.x+vA.y*vA.y+vA.z*vA.z+vA.w*vA.w;
        float dB0 = vB.x*k0.x+vB.y*k0.y+vB.z*k0.z+vB.w*k0.w;
        float dB1 = vB.x*k1.x+vB.y*k1.y+vB.z*k1.z+vB.w*k1.w;
        float nnB = vB.x*vB.x+vB.y*vB.y+vB.z*vB.z+vB.w*vB.w;
        float dv = gred4(dA0,dA1,dB0,dB1,lane);
        float nv = gred2(nnA,nnB,lane);
        if (lane==0)  s_part[ii][wid]      = dv;
        if (lane==8)  s_part[ii][32+wid]   = dv;
        if (lane==16) s_part[ii+1][wid]    = dv;
        if (lane==24) s_part[ii+1][32+wid] = dv;
        if (lane==0)  s_part[ii][64+wid]   = nv;
        if (lane==16) s_part[ii+1][64+wid] = nv;
    }
    __syncthreads();
    if (tid < 96) {
        int row = tid/3, q = tid - row*3;
        float s = 0.f;
        #pragma unroll
        for (int k=0;k<32;k++) s += s_part[row][q*32+k];
        int m = base + row;
        if (q==0) g_dot[m]=s; else if (q==1) g_dot[MM+m]=s; else g_memnorm[m]=sqrtf(s);
    }
}

// ------------- kernel 3a: content weights (per write head, parallel) -------
__global__ void k_cw(){
    __shared__ float red[32];
    __shared__ float s_bc;
    const int T = 1024;
    int tid=threadIdx.x, lane=tid&31, wid=tid>>5;
    int head = blockIdx.x;
    float kn=0.f;
    for (int d=tid; d<WORDD; d+=T){ float k = g_wk[head*WORDD+d]; kn += k*k; }
    kn = wred(kn);
    if (lane==0) red[wid]=kn;
    __syncthreads();
    if (tid==0){ float s=0; for(int k=0;k<32;k++) s+=red[k]; s_bc = sqrtf(s);}
    __syncthreads();
    kn = s_bc;
    float ws = g_small[28+head];
    float beta = 1.f + log1pf(expf(ws));
    float mx = -3.4e38f;
    for (int m=tid;m<MM;m+=T){
        float l = g_dot[head*MM+m]/(kn*g_memnorm[m]+EPSV)*beta;
        mx = fmaxf(mx,l);
    }
    #pragma unroll
    for (int o=16;o;o>>=1) mx = fmaxf(mx,__shfl_xor_sync(0xFFFFFFFFu,mx,o));
    if (lane==0) red[wid]=mx;
    __syncthreads();
    if (tid==0){ float s=-3.4e38f; for(int k=0;k<32;k++) s=fmaxf(s,red[k]); s_bc=s;}
    __syncthreads();
    mx = s_bc;
    float sume=0.f;
    for (int m=tid;m<MM;m+=T){
        float l = g_dot[head*MM+m]/(kn*g_memnorm[m]+EPSV)*beta;
        float e = expf(l-mx);
        g_cw[head*MM+m]=e; sume+=e;
    }
    sume = wred(sume);
    if (lane==0) red[wid]=sume;
    __syncthreads();
    if (tid==0){ float s=0; for(int k=0;k<32;k++) s+=red[k]; s_bc=s;}
    __syncthreads();
    float inv = 1.f/s_bc;
    for (int m=tid;m<MM;m+=T) g_cw[head*MM+m] *= inv;
}

// ------------- kernel 3b: initial usage ------------------------------------
__global__ void k_usage(const float* __restrict__ prev_rw,
                        const float* __restrict__ prev_ww,
                        const float* __restrict__ prev_usage){
    int m = blockIdx.x*1024 + threadIdx.x;
    float fg0=g_small[0],fg1=g_small[1],fg2=g_small[2],fg3=g_small[3];
    float u = prev_usage[m];
    u = u + (1.f-u)*(1.f - prev_ww[m]*prev_ww[MM+m]);
    float p = (fg0*prev_rw[m])*(fg1*prev_rw[MM+m])*(fg2*prev_rw[2*MM+m])*(fg3*prev_rw[3*MM+m]);
    g_usageA[m] = u*(1.f - p);
}

// ------------- kernel 3c: partial rank counts (grid 4 x 32, no atomics) ----
__global__ void __launch_bounds__(1024) k_rankpart(int which){
    __shared__ unsigned long long s_k[128];
    const float* usage_in = which ? g_usageB : g_usageA;
    int tid = threadIdx.x;
    int bj = blockIdx.y;
    if (tid < 128){
        int j = bj*128 + tid;
        float u = EPSV + (1.f-EPSV)*usage_in[j];
        s_k[tid] = ((unsigned long long)__float_as_uint(u) << 32) | (unsigned)j;
    }
    __syncthreads();
    int m = blockIdx.x*1024 + tid;
    float um = EPSV + (1.f-EPSV)*usage_in[m];
    unsigned long long km = ((unsigned long long)__float_as_uint(um) << 32) | (unsigned)m;
    int cnt = 0;
    #pragma unroll
    for (int j=0;j<128;j++) cnt += (s_k[j] < km);
    g_partcnt[bj*MM + m] = cnt;
}

// ------------- kernel 3c2: sum partials + scatter sorted key ---------------
__global__ void __launch_bounds__(1024) k_scatter(int which){
    const float* usage_in = which ? g_usageB : g_usageA;
    int m = blockIdx.x*1024 + threadIdx.x;
    int cnt = 0;
    #pragma unroll
    for (int c=0;c<32;c++) cnt += g_partcnt[c*MM + m];
    float um = EPSV + (1.f-EPSV)*usage_in[m];
    g_sortedu[cnt] = um;
    g_rankidx[m] = cnt;
}

// ------------- kernel 3d: cumprod scan over sorted u + alloc + usage upd ---
__global__ void __launch_bounds__(1024) k_scan(int head,
                                               float* __restrict__ out_usage_final){
    __shared__ float s_alloc[MM];
    __shared__ float s_wsum2[32];
    __shared__ float s_wpre[32];
    const float* usage_in = head ? g_usageB : g_usageA;
    int tid=threadIdx.x, lane=tid&31, wid=tid>>5;
    int base = tid*4;
    float4 xv = *(const float4*)(g_sortedu + base);
    float x0=xv.x, x1=xv.y, x2=xv.z, x3=xv.w;
    float c0=x0, c1=c0*x1, c2=c1*x2, c3=c2*x3;
    float t3=c3;
    #pragma unroll
    for (int o=1;o<32;o<<=1){ float n=__shfl_up_sync(0xFFFFFFFFu,t3,o); if (lane>=o) t3*=n; }
    float warpExcl = __shfl_up_sync(0xFFFFFFFFu,t3,1); if (lane==0) warpExcl=1.f;
    if (lane==31) s_wsum2[wid]=t3;
    __syncthreads();
    if (tid<32){
        float w = s_wsum2[tid];
        float tw=w;
        #pragma unroll
        for (int o=1;o<32;o<<=1){ float n=__shfl_up_sync(0xFFFFFFFFu,tw,o); if (tid>=o) tw*=n; }
        float excl = __shfl_up_sync(0xFFFFFFFFu,tw,1); if (tid==0) excl=1.f;
        s_wpre[tid]=excl;
    }
    __syncthreads();
    float pre = s_wpre[wid]*warpExcl;
    s_alloc[base+0]=(1.f-x0)*pre;
    s_alloc[base+1]=(1.f-x1)*pre*c0;
    s_alloc[base+2]=(1.f-x2)*pre*c1;
    s_alloc[base+3]=(1.f-x3)*pre*c2;
    __syncthreads();
    float ag=g_small[4+head], wg=g_small[6+head];
    float agwg = ag*wg;
    for (int m=tid;m<MM;m+=1024){
        float a = s_alloc[g_rankidx[m]];
        g_alloc[head*MM+m] = a;
        float u = usage_in[m];
        float nu = u + (1.f - u)*agwg*a;
        if (head==0) g_usageB[m] = nu; else out_usage_final[m] = nu;
    }
}

// ------------- kernel 3e: write weights + precedence (per head) ------------
__global__ void k_wwprec(const float* __restrict__ prev_prec,
                         float* __restrict__ out_ww,
                         float* __restrict__ out_prec)
{
    __shared__ float red[32];
    __shared__ float s_bc;
    const int T = 1024;
    int tid=threadIdx.x, lane=tid&31, wid=tid>>5;
    int head = blockIdx.x;
    float ag = g_small[4+head], wg = g_small[6+head];
    float wsum = 0.f;
    for (int m=tid;m<MM;m+=T){
        float a = g_alloc[head*MM+m];
        float cw = g_cw[head*MM+m];
        float w = wg*(ag*a + (1.f-ag)*cw);
        g_ww[head*MM+m] = w;
        out_ww[head*MM+m] = w;
        wsum += w;
    }
    wsum = wred(wsum);
    if (lane==0) red[wid]=wsum;
    __syncthreads();
    if (tid==0){ float s=0; for(int k=0;k<32;k++) s+=red[k]; s_bc=s;}
    __syncthreads();
    float oms = 1.f - s_bc;
    for (int m=tid;m<MM;m+=T)
        out_prec[head*MM+m] = oms*prev_prec[head*MM+m] + g_ww[head*MM+m];
}

// ------------- kernel 4: new_memory + fused rdot + new norms ---------------
__global__ void __launch_bounds__(1024) k_newmem(const float* __restrict__ memory,
                                                 float* __restrict__ out_nm){
    __shared__ float s_part[32][5*32];
    int tid=threadIdx.x, lane=tid&31, wid=tid>>5;
    const float4* ev4=(const float4*)g_ev;
    const float4* wv4=(const float4*)g_wv;
    const float4* rk4=(const float4*)g_rk;
    float4 e0=__ldg(&ev4[tid]),      e1=__ldg(&ev4[1024+tid]);
    float4 a0=__ldg(&wv4[tid]),      a1=__ldg(&wv4[1024+tid]);
    float4 k0=__ldg(&rk4[tid]),      k1=__ldg(&rk4[1024+tid]);
    float4 k2=__ldg(&rk4[2048+tid]), k3=__ldg(&rk4[3072+tid]);
    int base = blockIdx.x*32;
    float4 v_next = __ldg((const float4*)(memory+(size_t)base*WORDD) + tid);
    #pragma unroll 1
    for (int ii=0; ii<32; ii++){
        int m = base+ii;
        float4 v = v_next;
        if (ii<31) v_next = __ldg((const float4*)(memory+(size_t)(m+1)*WORDD) + tid);
        float w0=__ldg(&g_ww[m]), w1=__ldg(&g_ww[MM+m]);
        float4 o;
        o.x = v.x*((1.f-w0*e0.x)*(1.f-w1*e1.x)) + w0*a0.x + w1*a1.x;
        o.y = v.y*((1.f-w0*e0.y)*(1.f-w1*e1.y)) + w0*a0.y + w1*a1.y;
        o.z = v.z*((1.f-w0*e0.z)*(1.f-w1*e1.z)) + w0*a0.z + w1*a1.z;
        o.w = v.w*((1.f-w0*e0.w)*(1.f-w1*e1.w)) + w0*a0.w + w1*a1.w;
        ((float4*)(out_nm+(size_t)m*WORDD))[tid]=o;
        float r0 = o.x*k0.x+o.y*k0.y+o.z*k0.z+o.w*k0.w;
        float r1 = o.x*k1.x+o.y*k1.y+o.z*k1.z+o.w*k1.w;
        float r2 = o.x*k2.x+o.y*k2.y+o.z*k2.z+o.w*k2.w;
        float r3 = o.x*k3.x+o.y*k3.y+o.z*k3.z+o.w*k3.w;
        float nn = o.x*o.x+o.y*o.y+o.z*o.z+o.w*o.w;
        float rv = gred4(r0,r1,r2,r3,lane);
        float nv = wred(nn);
        if ((lane&7)==0) s_part[ii][(lane>>3)*32+wid] = rv;
        if (lane==0)     s_part[ii][128+wid] = nv;
    }
    __syncthreads();
    if (tid < 160){
        int row=tid/5, q=tid-row*5;
        float s=0.f;
        #pragma unroll
        for (int k=0;k<32;k++) s += s_part[row][q*32+k];
        int m = base + row;
        if (q<4) g_rdot[q*MM+m]=s; else g_newnorm[m]=sqrtf(s);
    }
}

// ------------- kernel 5: link update + fused fwd_w/bwd_w -------------------
__global__ void __launch_bounds__(512) k_link(const float* __restrict__ prev_link,
                       const float* __restrict__ prev_prec,
                       const float* __restrict__ prev_rw,
                       float* __restrict__ out_link){
    __shared__ float s_fred[LCHUNK][4][16];
    int w = blockIdx.y;
    int chunk = blockIdx.x;
    int i0 = chunk*LCHUNK;
    int tid=threadIdx.x, lane=tid&31, wid=tid>>5;
    const float4* ww4 = (const float4*)(g_ww + w*MM);
    const float4* pp4 = (const float4*)(prev_prec + w*MM);
    const float4* pr4 = (const float4*)prev_rw;
    float4 wwa=__ldg(&ww4[tid]),       wwb=__ldg(&ww4[512+tid]);
    float4 ppa=__ldg(&pp4[tid]),       ppb=__ldg(&pp4[512+tid]);
    float4 pa0=__ldg(&pr4[tid]),       pb0=__ldg(&pr4[512+tid]);
    float4 pa1=__ldg(&pr4[1024+tid]),  pb1=__ldg(&pr4[1536+tid]);
    float4 pa2=__ldg(&pr4[2048+tid]),  pb2=__ldg(&pr4[2560+tid]);
    float4 pa3=__ldg(&pr4[3072+tid]),  pb3=__ldg(&pr4[3584+tid]);
    float bw0[8],bw1[8],bw2[8],bw3[8];
    #pragma unroll
    for (int c=0;c<8;c++){ bw0[c]=0.f;bw1[c]=0.f;bw2[c]=0.f;bw3[c]=0.f; }
    int ja = tid*4, jb = (512+tid)*4;
    const float4* plbase = (const float4*)(prev_link + (size_t)w*MM*MM);
    float4 pA_n = __ldcs(plbase + (size_t)i0*1024 + tid);
    float4 pB_n = __ldcs(plbase + (size_t)i0*1024 + 512 + tid);
    #pragma unroll 1
    for (int ii=0; ii<LCHUNK; ii++){
        int i = i0+ii;
        float4 pA = pA_n, pB = pB_n;
        if (ii<LCHUNK-1){
            pA_n = __ldcs(plbase + (size_t)(i+1)*1024 + tid);
            pB_n = __ldcs(plbase + (size_t)(i+1)*1024 + 512 + tid);
        }
        float wwi = __ldg(&g_ww[w*MM+i]);
        float pri0=__ldg(&prev_rw[i]),      pri1=__ldg(&prev_rw[MM+i]);
        float pri2=__ldg(&prev_rw[2*MM+i]), pri3=__ldg(&prev_rw[3*MM+i]);
        float f0=0.f,f1=0.f,f2=0.f,f3=0.f;
        float4 oA, oB;
        {
            float l = (1.f-wwi-wwa.x)*pA.x + wwi*ppa.x; if (ja+0==i) l=0.f; oA.x=l;
            f0+=pa0.x*l; f1+=pa1.x*l; f2+=pa2.x*l; f3+=pa3.x*l;
            bw0[0]+=pri0*l; bw1[0]+=pri1*l; bw2[0]+=pri2*l; bw3[0]+=pri3*l;
        }
        {
            float l = (1.f-wwi-wwa.y)*pA.y + wwi*ppa.y; if (ja+1==i) l=0.f; oA.y=l;
            f0+=pa0.y*l; f1+=pa1.y*l; f2+=pa2.y*l; f3+=pa3.y*l;
            bw0[1]+=pri0*l; bw1[1]+=pri1*l; bw2[1]+=pri2*l; bw3[1]+=pri3*l;
        }
        {
            float l = (1.f-wwi-wwa.z)*pA.z + wwi*ppa.z; if (ja+2==i) l=0.f; oA.z=l;
            f0+=pa0.z*l; f1+=pa1.z*l; f2+=pa2.z*l; f3+=pa3.z*l;
            bw0[2]+=pri0*l; bw1[2]+=pri1*l; bw2[2]+=pri2*l; bw3[2]+=pri3*l;
        }
        {
            float l = (1.f-wwi-wwa.w)*pA.w + wwi*ppa.w; if (ja+3==i) l=0.f; oA.w=l;
            f0+=pa0.w*l; f1+=pa1.w*l; f2+=pa2.w*l; f3+=pa3.w*l;
            bw0[3]+=pri0*l; bw1[3]+=pri1*l; bw2[3]+=pri2*l; bw3[3]+=pri3*l;
        }
        {
            float l = (1.f-wwi-wwb.x)*pB.x + wwi*ppb.x; if (jb+0==i) l=0.f; oB.x=l;
            f0+=pb0.x*l; f1+=pb1.x*l; f2+=pb2.x*l; f3+=pb3.x*l;
            bw0[4]+=pri0*l; bw1[4]+=pri1*l; bw2[4]+=pri2*l; bw3[4]+=pri3*l;
        }
        {
            float l = (1.f-wwi-wwb.y)*pB.y + wwi*ppb.y; if (jb+1==i) l=0.f; oB.y=l;
            f0+=pb0.y*l; f1+=pb1.y*l; f2+=pb2.y*l; f3+=pb3.y*l;
            bw0[5]+=pri0*l; bw1[5]+=pri1*l; bw2[5]+=pri2*l; bw3[5]+=pri3*l;
        }
        {
            float l = (1.f-wwi-wwb.z)*pB.z + wwi*ppb.z; if (jb+2==i) l=0.f; oB.z=l;
            f0+=pb0.z*l; f1+=pb1.z*l; f2+=pb2.z*l; f3+=pb3.z*l;
            bw0[6]+=pri0*l; bw1[6]+=pri1*l; bw2[6]+=pri2*l; bw3[6]+=pri3*l;
        }
        {
            float l = (1.f-wwi-wwb.w)*pB.w + wwi*ppb.w; if (jb+3==i) l=0.f; oB.w=l;
            f0+=pb0.w*l; f1+=pb1.w*l; f2+=pb2.w*l; f3+=pb3.w*l;
            bw0[7]+=pri0*l; bw1[7]+=pri1*l; bw2[7]+=pri2*l; bw3[7]+=pri3*l;
        }
        float4* lo = (float4*)(out_link + ((size_t)w*MM+i)*MM);
        __stcs(lo + tid, oA);
        __stcs(lo + 512 + tid, oB);
        float fv = gred4(f0,f1,f2,f3,lane);
        if ((lane&7)==0) s_fred[ii][lane>>3][wid]=fv;
    }
    __syncthreads();
    if (tid < LCHUNK*4){
        int row = tid>>2, r = tid&3;
        float s=0.f;
        #pragma unroll
        for (int k=0;k<16;k++) s += s_fred[row][r][k];
        g_fwd[(r*NWH + w)*MM + i0 + row] = s;
    }
    size_t pb = (size_t)(w*LNCH + chunk)*4;
    ((float4*)(g_part_bwd + (pb+0)*MM))[tid]     = make_float4(bw0[0],bw0[1],bw0[2],bw0[3]);
    ((float4*)(g_part_bwd + (pb+0)*MM))[512+tid] = make_float4(bw0[4],bw0[5],bw0[6],bw0[7]);
    ((float4*)(g_part_bwd + (pb+1)*MM))[tid]     = make_float4(bw1[0],bw1[1],bw1[2],bw1[3]);
    ((float4*)(g_part_bwd + (pb+1)*MM))[512+tid] = make_float4(bw1[4],bw1[5],bw1[6],bw1[7]);
    ((float4*)(g_part_bwd + (pb+2)*MM))[tid]     = make_float4(bw2[0],bw2[1],bw2[2],bw2[3]);
    ((float4*)(g_part_bwd + (pb+2)*MM))[512+tid] = make_float4(bw2[4],bw2[5],bw2[6],bw2[7]);
    ((float4*)(g_part_bwd + (pb+3)*MM))[tid]     = make_float4(bw3[0],bw3[1],bw3[2],bw3[3]);
    ((float4*)(g_part_bwd + (pb+3)*MM))[512+tid] = make_float4(bw3[4],bw3[5],bw3[6],bw3[7]);
}

// ------------- kernel 6: reduce bwd partials (fixed order, deterministic) --
__global__ void k_bwdreduce(){
    int idx = blockIdx.x*blockDim.x + threadIdx.x; // 32768
    if (idx >= RH*NWH*MM) return;
    int m = idx & (MM-1);
    int w = (idx >> 12) & 1;
    int r = idx >> 13;
    float s=0.f;
    #pragma unroll 8
    for (int t=0;t<LNCH;t++)
        s += g_part_bwd[((size_t)(w*LNCH+t)*4 + r)*MM + m];
    g_bwd[idx]=s;
}

// ------------- kernel 7: read weights — one block per read head -----------
__global__ void k_readw(float* __restrict__ out_rw){
    __shared__ float s_e[MM];
    __shared__ float red[32];
    __shared__ float s_bc;
    const int T = 1024;
    int tid=threadIdx.x, lane=tid&31, wid=tid>>5;
    int r = blockIdx.x;
    float kn=0.f;
    for (int d=tid;d<WORDD;d+=T){ float k=g_rk[r*WORDD+d]; kn+=k*k; }
    kn = wred(kn);
    if (lane==0) red[wid]=kn;
    __syncthreads();
    if (tid==0){ float s=0; for(int k=0;k<32;k++) s+=red[k]; s_bc=sqrtf(s);}
    __syncthreads();
    kn=s_bc;
    float rs = g_small[30+r];
    float mx=-3.4e38f;
    for (int m=tid;m<MM;m+=T){
        float l = g_rdot[r*MM+m]/(kn*g_newnorm[m])*rs;
        mx=fmaxf(mx,l);
    }
    #pragma unroll
    for (int o=16;o;o>>=1) mx=fmaxf(mx,__shfl_xor_sync(0xFFFFFFFFu,mx,o));
    if (lane==0) red[wid]=mx;
    __syncthreads();
    if (tid==0){ float s=-3.4e38f; for(int k=0;k<32;k++) s=fmaxf(s,red[k]); s_bc=s;}
    __syncthreads();
    mx=s_bc;
    float sume=0.f;
    for (int m=tid;m<MM;m+=T){
        float l = g_rdot[r*MM+m]/(kn*g_newnorm[m])*rs;
        float e = expf(l-mx);
        s_e[m]=e; sume+=e;
    }
    sume = wred(sume);
    if (lane==0) red[wid]=sume;
    __syncthreads();
    if (tid==0){ float s=0; for(int k=0;k<32;k++) s+=red[k]; s_bc=s;}
    __syncthreads();
    float inv = 1.f/s_bc;
    float bm0=g_small[8+r*5+0], bm1=g_small[8+r*5+1];
    float fm0=g_small[8+r*5+2], fm1=g_small[8+r*5+3];
    float cm =g_small[8+r*5+4];
    for (int m=tid;m<MM;m+=T){
        float v = bm0*g_bwd[(r*2+0)*MM+m] + bm1*g_bwd[(r*2+1)*MM+m]
                + fm0*g_fwd[(r*2+0)*MM+m] + fm1*g_fwd[(r*2+1)*MM+m]
                + cm*s_e[m]*inv;
        g_rw[r*MM+m]=v; out_rw[r*MM+m]=v;
    }
}

// ------------- kernel 8: read_words partials -------------------------------
__global__ void k_readwords(const float* __restrict__ nm){
    __shared__ float s_rw[4][256];
    int d = blockIdx.x*256 + threadIdx.x;
    int m0 = blockIdx.y*256;
    #pragma unroll
    for (int r=0;r<4;r++) s_rw[r][threadIdx.x] = g_rw[r*MM + m0 + threadIdx.x];
    __syncthreads();
    float a0=0,a1=0,a2=0,a3=0;
    #pragma unroll 4
    for (int mm=0;mm<256;mm++){
        float v = nm[(size_t)(m0+mm)*WORDD + d];
        a0+=s_rw[0][mm]*v; a1+=s_rw[1][mm]*v; a2+=s_rw[2][mm]*v; a3+=s_rw[3][mm]*v;
    }
    g_part_rw[(blockIdx.y*4+0)*WORDD+d]=a0;
    g_part_rw[(blockIdx.y*4+1)*WORDD+d]=a1;
    g_part_rw[(blockIdx.y*4+2)*WORDD+d]=a2;
    g_part_rw[(blockIdx.y*4+3)*WORDD+d]=a3;
}

// ------------- kernel 9: reduce read_words partials ------------------------
__global__ void k_rwreduce(float* __restrict__ out_rwords){
    int idx = blockIdx.x*blockDim.x+threadIdx.x; // 16384
    if (idx >= RH*WORDD) return;
    int r = idx >> 12; int d = idx & (WORDD-1);
    float s=0.f;
    #pragma unroll
    for (int t=0;t<16;t++) s += g_part_rw[(t*4+r)*WORDD+d];
    out_rwords[idx]=s;
}

// ---------------------------------------------------------------------------
extern "C" void kernel_launch(void* const* d_in, const int* in_sizes, int n_in,
                              void* d_out, int out_size) {
    const float* x      = (const float*)d_in[0];
    const float* memory = (const float*)d_in[1];
    const float* prw    = (const float*)d_in[2];
    const float* pww    = (const float*)d_in[3];
    const float* plink  = (const float*)d_in[4];
    const float* pprec  = (const float*)d_in[5];
    const float* pusage = (const float*)d_in[6];

    float* out = (float*)d_out;
    float* o_rwords = out;                            // 4*4096
    float* o_nm     = out + 16384;                    // 4096*4096
    float* o_rw     = out + 16384 + 16777216;         // 4*4096
    float* o_ww     = o_rw + 16384;                   // 2*4096
    float* o_link   = o_ww + 8192;                    // 2*4096*4096
    float* o_prec   = o_link + 33554432;              // 2*4096
    float* o_usage  = o_prec + 8192;                  // 4096

    cudaStream_t s2;
    cudaStreamCreateWithFlags(&s2, cudaStreamNonBlocking);
    cudaEvent_t eMV, eQ, eS, eL;
    cudaEventCreateWithFlags(&eMV, cudaEventDisableTiming);
    cudaEventCreateWithFlags(&eQ, cudaEventDisableTiming);
    cudaEventCreateWithFlags(&eS, cudaEventDisableTiming);
    cudaEventCreateWithFlags(&eL, cudaEventDisableTiming);

    // 1. all linears (main)
    {
        int warps = 40994;
        int blocks = (warps*32 + 255)/256;
        k_matvec<<<blocks, 256>>>(x,
            (const float*)d_in[7],  (const float*)d_in[8],
            (const float*)d_in[9],  (const float*)d_in[10],
            (const float*)d_in[11], (const float*)d_in[12],
            (const float*)d_in[13], (const float*)d_in[14],
            (const float*)d_in[15], (const float*)d_in[16],
            (const float*)d_in[17], (const float*)d_in[18],
            (const float*)d_in[19], (const float*)d_in[20],
            (const float*)d_in[21], (const float*)d_in[22],
            (const float*)d_in[23], (const float*)d_in[24],
            (const float*)d_in[25], (const float*)d_in[26]);
    }
    cudaEventRecord(eMV, 0);
    // s2: sort chain (needs only matvec scalars + prev inputs)
    cudaStreamWaitEvent(s2, eMV, 0);
    k_usage<<<4, 1024, 0, s2>>>(prw, pww, pusage);
    k_rankpart<<<dim3(4,32), 1024, 0, s2>>>(0);
    k_scatter<<<4, 1024, 0, s2>>>(0);
    k_scan<<<1, 1024, 0, s2>>>(0, o_usage);
    k_rankpart<<<dim3(4,32), 1024, 0, s2>>>(1);
    k_scatter<<<4, 1024, 0, s2>>>(1);
    k_scan<<<1, 1024, 0, s2>>>(1, o_usage);
    cudaEventRecord(eQ, s2);
    // main: memdot + content weights (concurrent with sort chain)
    k_memdot<<<128, 1024>>>(memory);
    k_cw<<<2, 1024>>>();
    // join: wwprec needs alloc (s2) + cw (main)
    cudaStreamWaitEvent(0, eQ, 0);
    k_wwprec<<<2, 1024>>>(pprec, o_ww, o_prec);
    cudaEventRecord(eS, 0);
    // link on s2 ∥ newmem on main
    cudaStreamWaitEvent(s2, eS, 0);
    k_link<<<dim3(LNCH,2), 512, 0, s2>>>(plink, pprec, prw, o_link);
    cudaEventRecord(eL, s2);
    k_newmem<<<128, 1024>>>(memory, o_nm);
    cudaStreamWaitEvent(0, eL, 0);
    // tail
    k_bwdreduce<<<128, 256>>>();
    k_readw<<<4, 1024>>>(o_rw);
    k_readwords<<<dim3(16,16), 256>>>(o_nm);
    k_rwreduce<<<64, 256>>>(o_rwords);
}